// round 13
// baseline (speedup 1.0000x reference)
#include <cuda_runtime.h>
#include <cuda_bf16.h>
#include <cstdint>

#define NB 2
#define L  4096
#define D  512
#define H  8
#define DH 64

#define SCALE 0.18033688011111793f  /* log2(e)/8 */

__device__ unsigned short g_qh[NB*H*L*DH], g_ql[NB*H*L*DH];
__device__ unsigned short g_kh[NB*H*L*DH], g_kl[NB*H*L*DH];
__device__ unsigned short g_vh[NB*H*L*DH], g_vl[NB*H*L*DH];   // fp16 hi/lo
__device__ unsigned short g_aoh[NB*H*L*DH], g_aol[NB*H*L*DH];
__device__ unsigned short g_wh[4*D*D], g_wl[4*D*D];
__device__ float g_wb[4*D];
__device__ int   g_allones[NB*L];

// ------------------------------ helpers ------------------------------------
__device__ __forceinline__ uint32_t su32(const void* p) {
    uint32_t a;
    asm("{ .reg .u64 t; cvta.to.shared.u64 t, %1; cvt.u32.u64 %0, t; }" : "=r"(a) : "l"(p));
    return a;
}
__device__ __forceinline__ float ex2(float x) {
    float r; asm("ex2.approx.f32 %0, %1;" : "=f"(r) : "f"(x)); return r;
}
__device__ __forceinline__ void packsplit(float f0, float f1, uint32_t& hp, uint32_t& lp) {
    asm("cvt.rn.bf16x2.f32 %0, %1, %2;" : "=r"(hp) : "f"(f1), "f"(f0));
    float r0 = __uint_as_float(hp << 16);
    float r1 = __uint_as_float(hp & 0xffff0000u);
    float l0 = f0 - r0, l1 = f1 - r1;
    asm("cvt.rn.bf16x2.f32 %0, %1, %2;" : "=r"(lp) : "f"(l1), "f"(l0));
}
__device__ __forceinline__ uint32_t packf16(float f0, float f1) {
    uint32_t r;
    asm("cvt.rn.f16x2.f32 %0, %1, %2;" : "=r"(r) : "f"(f1), "f"(f0));
    return r;
}
__device__ __forceinline__ void packsplit_f16(float f0, float f1, uint32_t& hp, uint32_t& lp) {
    asm("cvt.rn.f16x2.f32 %0, %1, %2;" : "=r"(hp) : "f"(f1), "f"(f0));
    float r0, r1;
    asm("{ .reg .b16 lo, hi; mov.b32 {lo, hi}, %2; cvt.f32.f16 %0, lo; cvt.f32.f16 %1, hi; }"
        : "=f"(r0), "=f"(r1) : "r"(hp));
    asm("cvt.rn.f16x2.f32 %0, %1, %2;" : "=r"(lp) : "f"(f1 - r1), "f"(f0 - r0));
}
__device__ __forceinline__ void ldsm4(uint32_t& r0, uint32_t& r1, uint32_t& r2, uint32_t& r3, uint32_t a) {
    asm volatile("ldmatrix.sync.aligned.m8n8.x4.shared.b16 {%0,%1,%2,%3}, [%4];"
        : "=r"(r0), "=r"(r1), "=r"(r2), "=r"(r3) : "r"(a));
}
__device__ __forceinline__ void ldsm4t(uint32_t& r0, uint32_t& r1, uint32_t& r2, uint32_t& r3, uint32_t a) {
    asm volatile("ldmatrix.sync.aligned.m8n8.x4.trans.shared.b16 {%0,%1,%2,%3}, [%4];"
        : "=r"(r0), "=r"(r1), "=r"(r2), "=r"(r3) : "r"(a));
}
__device__ __forceinline__ void mma16816(float c[4], const uint32_t a[4], uint32_t b0, uint32_t b1) {
    asm volatile("mma.sync.aligned.m16n8k16.row.col.f32.bf16.bf16.f32 "
        "{%0,%1,%2,%3},{%4,%5,%6,%7},{%8,%9},{%0,%1,%2,%3};"
        : "+f"(c[0]), "+f"(c[1]), "+f"(c[2]), "+f"(c[3])
        : "r"(a[0]), "r"(a[1]), "r"(a[2]), "r"(a[3]), "r"(b0), "r"(b1));
}
__device__ __forceinline__ void mma16816f(float c[4], const uint32_t a[4], uint32_t b0, uint32_t b1) {
    asm volatile("mma.sync.aligned.m16n8k16.row.col.f32.f16.f16.f32 "
        "{%0,%1,%2,%3},{%4,%5,%6,%7},{%8,%9},{%0,%1,%2,%3};"
        : "+f"(c[0]), "+f"(c[1]), "+f"(c[2]), "+f"(c[3])
        : "r"(a[0]), "r"(a[1]), "r"(a[2]), "r"(a[3]), "r"(b0), "r"(b1));
}
__device__ __forceinline__ void cpa16(uint32_t dst, const void* src) {
    asm volatile("cp.async.cg.shared.global [%0], [%1], 16;"
        :: "r"(dst), "l"(__cvta_generic_to_global(src)));
}
#define CPCOMMIT() asm volatile("cp.async.commit_group;" ::: "memory")
#define CPWAIT0()  asm volatile("cp.async.wait_group 0;" ::: "memory")

// ------------------------------ mask pre-scan ------------------------------
__global__ void mask_scan(const int* __restrict__ mask) {
    int row = blockIdx.x;
    const int4* m = (const int4*)(mask + (size_t)row * L);
    int ok = 1;
    for (int i = threadIdx.x; i < L/4; i += 256) {
        int4 v = m[i];
        ok &= (v.x != 0) & (v.y != 0) & (v.z != 0) & (v.w != 0);
    }
    ok = __syncthreads_and(ok);
    if (threadIdx.x == 0) g_allones[row] = ok;
}

// --------------------- weight prep: bf16 hi/lo split ------------------------
__global__ void prep_w(const float* __restrict__ Wq, const float* __restrict__ Wk,
                       const float* __restrict__ Wv, const float* __restrict__ Wo,
                       const float* __restrict__ bq, const float* __restrict__ bk,
                       const float* __restrict__ bv, const float* __restrict__ bo) {
    int idx = blockIdx.x * 256 + threadIdx.x;
    int mat = idx >> 18;
    int rem = idx & 262143;
    const float* W = (mat==0) ? Wq : (mat==1) ? Wk : (mat==2) ? Wv : Wo;
    float v = W[rem];
    if (mat == 0) v *= SCALE;
    __nv_bfloat16 hb = __float2bfloat16(v);
    float r = __bfloat162float(hb);
    __nv_bfloat16 lb = __float2bfloat16(v - r);
    g_wh[idx] = *(unsigned short*)&hb;
    g_wl[idx] = *(unsigned short*)&lb;
    if (idx < 4*D) {
        int m2 = idx >> 9, n = idx & 511;
        const float* B = (m2==0) ? bq : (m2==1) ? bk : (m2==2) ? bv : bo;
        float bvl = B[n];
        if (m2 == 0) bvl *= SCALE;
        g_wb[idx] = bvl;
    }
}

// ---------------- QKV projections via mma.sync bf16x3 -----------------------
#define PJ_XH 0
#define PJ_XL 18432
#define PJ_WH 36864
#define PJ_WL 46080
#define PJ_SZ 55296

__global__ void __launch_bounds__(256) proj_mma(const float* __restrict__ xq,
                                                const float* __restrict__ xk,
                                                const float* __restrict__ xv) {
    extern __shared__ char smem[];
    const uint32_t sb = su32(smem);
    const int tid = threadIdx.x;
    const int w = tid >> 5, l = tid & 31;
    const int g = l >> 2, cc = l & 3;
    const int m0 = blockIdx.x * 128;
    const int head = blockIdx.y;
    const int z = blockIdx.z;
    const int n0 = head * 64;
    const float* X = (z==0) ? xq : (z==1) ? xk : xv;

    const int warr = tid >> 7;
    const int wrow = (tid >> 1) & 63;
    const int wseg0 = (tid & 1) * 4;
    const unsigned short* wsrc = (warr ? g_wl : g_wh) + (size_t)z*262144 + (size_t)(n0 + wrow)*512;
    const uint32_t wdst = sb + (warr ? PJ_WL : PJ_WH) + wrow*144;

    const int xrow = tid >> 1, xhalf = tid & 1;

    float c[8][4] = {};
    for (int kt = 0; kt < 8; kt++) {
        #pragma unroll
        for (int i = 0; i < 4; i++) {
            int seg = wseg0 + i;
            cpa16(wdst + seg*16, wsrc + kt*64 + seg*8);
        }
        CPCOMMIT();
        #pragma unroll
        for (int jj = 0; jj < 8; jj++) {
            int col = xhalf*32 + jj*4;
            float4 v = *(const float4*)(X + (size_t)(m0 + xrow)*512 + kt*64 + col);
            uint32_t h0,l0,h1,l1;
            packsplit(v.x, v.y, h0, l0); packsplit(v.z, v.w, h1, l1);
            *(uint2*)(smem + PJ_XH + xrow*144 + col*2) = make_uint2(h0, h1);
            *(uint2*)(smem + PJ_XL + xrow*144 + col*2) = make_uint2(l0, l1);
        }
        CPWAIT0();
        __syncthreads();

        uint32_t ah[4][4], al[4][4];
        const uint32_t aoff = (uint32_t)((l & 15) + 16*w) * 144 + (uint32_t)(l >> 4) * 16;
        #pragma unroll
        for (int ks = 0; ks < 4; ks++) {
            ldsm4(ah[ks][0], ah[ks][1], ah[ks][2], ah[ks][3], sb + PJ_XH + aoff + ks*32);
            ldsm4(al[ks][0], al[ks][1], al[ks][2], al[ks][3], sb + PJ_XL + aoff + ks*32);
        }
        const uint32_t boff = (uint32_t)(l & 7) * 144 + (uint32_t)(l >> 3) * 16;
        #pragma unroll
        for (int j = 0; j < 8; j++) {
            uint32_t kb[8], kbl[8];
            uint32_t bh_ = sb + PJ_WH + (uint32_t)(8*j)*144 + boff;
            uint32_t bl_ = sb + PJ_WL + (uint32_t)(8*j)*144 + boff;
            ldsm4(kb[0], kb[1], kb[2], kb[3], bh_);
            ldsm4(kb[4], kb[5], kb[6], kb[7], bh_ + 64);
            ldsm4(kbl[0], kbl[1], kbl[2], kbl[3], bl_);
            ldsm4(kbl[4], kbl[5], kbl[6], kbl[7], bl_ + 64);
            #pragma unroll
            for (int ks = 0; ks < 4; ks++) {
                mma16816(c[j], ah[ks], kb[2*ks],  kb[2*ks+1]);
                mma16816(c[j], ah[ks], kbl[2*ks], kbl[2*ks+1]);
                mma16816(c[j], al[ks], kb[2*ks],  kb[2*ks+1]);
            }
        }
        __syncthreads();
    }

    unsigned short* oh = (z==0) ? g_qh : (z==1) ? g_kh : g_vh;
    unsigned short* ol = (z==0) ? g_ql : (z==1) ? g_kl : g_vl;
    const int r0 = m0 + 16*w + g, r1 = r0 + 8;
    const int b0_ = r0 >> 12, l0_ = r0 & 4095;
    const int b1_ = r1 >> 12, l1_ = r1 & 4095;
    #pragma unroll
    for (int j = 0; j < 8; j++) {
        int col = 8*j + 2*cc;
        float bia0 = g_wb[z*512 + n0 + col], bia1 = g_wb[z*512 + n0 + col + 1];
        float v0a = c[j][0] + bia0, v1a = c[j][1] + bia1;
        float v0b = c[j][2] + bia0, v1b = c[j][3] + bia1;
        uint32_t hp, lp;
        if (z == 2) packsplit_f16(v0a, v1a, hp, lp);
        else        packsplit(v0a, v1a, hp, lp);
        size_t i0 = ((size_t)(b0_*H + head)*L + l0_)*64 + col;
        *(uint32_t*)(oh + i0) = hp; *(uint32_t*)(ol + i0) = lp;
        if (z == 2) packsplit_f16(v0b, v1b, hp, lp);
        else        packsplit(v0b, v1b, hp, lp);
        size_t i1 = ((size_t)(b1_*H + head)*L + l1_)*64 + col;
        *(uint32_t*)(oh + i1) = hp; *(uint32_t*)(ol + i1) = lp;
    }
}

// ---- attention (R11 base) + fused in-kernel normalization epilogue ---------
#define AT_BUF 36864   /* 4 arrays x 64 rows x 144B per buffer */

__global__ void __launch_bounds__(256) attn_mma(const int* __restrict__ mask,
                                                float* __restrict__ wout) {
    extern __shared__ char smem[];
    __shared__ float s_rinv[128];
    const uint32_t sb = su32(smem);
    const int tid = threadIdx.x;
    const int w = tid >> 5, l = tid & 31;
    const int g = l >> 2, cc = l & 3;
    const int qt = blockIdx.x, h = blockIdx.y, b = blockIdx.z;
    const int bh = b*H + h;
    const int q0 = qt * 128;
    const int r0 = q0 + 16*w + g, r1 = r0 + 8;

    uint32_t qh[4][4], ql[4][4];
    #pragma unroll
    for (int ks = 0; ks < 4; ks++) {
        int cA = 16*ks + 2*cc;
        size_t i00 = ((size_t)bh*L + r0)*64 + cA;
        size_t i10 = ((size_t)bh*L + r1)*64 + cA;
        qh[ks][0] = *(const uint32_t*)(g_qh + i00);
        qh[ks][1] = *(const uint32_t*)(g_qh + i10);
        qh[ks][2] = *(const uint32_t*)(g_qh + i00 + 8);
        qh[ks][3] = *(const uint32_t*)(g_qh + i10 + 8);
        ql[ks][0] = *(const uint32_t*)(g_ql + i00);
        ql[ks][1] = *(const uint32_t*)(g_ql + i10);
        ql[ks][2] = *(const uint32_t*)(g_ql + i00 + 8);
        ql[ks][3] = *(const uint32_t*)(g_ql + i10 + 8);
    }
    const bool ok0 = g_allones[(size_t)b*L + r0] != 0;
    const bool ok1 = g_allones[(size_t)b*L + r1] != 0;
    const int* mrow0 = mask + ((size_t)b*L + r0) * (size_t)L;
    const int* mrow1 = mask + ((size_t)b*L + r1) * (size_t)L;

    const int sarr = tid >> 6;          // 0 kh, 1 kl, 2 vh, 3 vl
    const int srow = tid & 63;
    const unsigned short* sbase = (sarr==0) ? g_kh : (sarr==1) ? g_kl : (sarr==2) ? g_vh : g_vl;
    const unsigned short* ssrc = sbase + ((size_t)bh*L + srow)*64;
    const uint32_t sdst = sb + sarr*9216 + srow*144;

    const uint32_t koff = (uint32_t)(l & 7) * 144 + (uint32_t)(l >> 3) * 16;
    const uint32_t voff = (uint32_t)((l & 7) + 8*(l >> 3)) * 144;

    float* w0 = wout + ((size_t)bh*L + r0) * (size_t)L;
    float* w1 = wout + ((size_t)bh*L + r1) * (size_t)L;

    float oacc[8][4] = {};
    float rs0 = 0.f, rs1 = 0.f;

    // prologue: stage k-tile 0 into buffer 0
    #pragma unroll
    for (int sgi = 0; sgi < 8; sgi++) cpa16(sdst + sgi*16, ssrc + sgi*8);
    CPCOMMIT();

    for (int it = 0; it < 64; it++) {
        const int kc = it * 64;
        CPWAIT0();
        __syncthreads();
        if (it + 1 < 64) {
            const int nb_ = (it + 1) & 1;
            const unsigned short* s2 = ssrc + (size_t)(kc + 64)*64;
            #pragma unroll
            for (int sgi = 0; sgi < 8; sgi++) cpa16(sdst + nb_*AT_BUF + sgi*16, s2 + sgi*8);
            CPCOMMIT();
        }
        const uint32_t bufb = sb + (it & 1)*AT_BUF;
        const uint32_t khb = bufb, klb = bufb + 9216, vhb = bufb + 18432, vlb = bufb + 27648;

        uint32_t ph[4][4];
        #pragma unroll
        for (int j = 0; j < 8; j++) {
            uint32_t kb[8], kbl[8];
            uint32_t ah = khb + (uint32_t)(8*j)*144 + koff;
            uint32_t al = klb + (uint32_t)(8*j)*144 + koff;
            ldsm4(kb[0], kb[1], kb[2], kb[3], ah);
            ldsm4(kb[4], kb[5], kb[6], kb[7], ah + 64);
            ldsm4(kbl[0], kbl[1], kbl[2], kbl[3], al);
            ldsm4(kbl[4], kbl[5], kbl[6], kbl[7], al + 64);
            float sacc[4] = {0.f, 0.f, 0.f, 0.f};
            #pragma unroll
            for (int ks = 0; ks < 4; ks++) {
                mma16816(sacc, qh[ks], kb[2*ks],  kb[2*ks+1]);
                mma16816(sacc, qh[ks], kbl[2*ks], kbl[2*ks+1]);
                mma16816(sacc, ql[ks], kb[2*ks],  kb[2*ks+1]);
            }
            float e0 = ex2(sacc[0]), e1 = ex2(sacc[1]);
            float e2 = ex2(sacc[2]), e3 = ex2(sacc[3]);
            int col = kc + 8*j + 2*cc;
            if (!ok0) {
                if (!mrow0[col])   e0 = 0.f;
                if (!mrow0[col+1]) e1 = 0.f;
            }
            if (!ok1) {
                if (!mrow1[col])   e2 = 0.f;
                if (!mrow1[col+1]) e3 = 0.f;
            }
            rs0 += e0 + e1; rs1 += e2 + e3;
            *(float2*)(w0 + col) = make_float2(e0, e1);       // unnormalized P
            *(float2*)(w1 + col) = make_float2(e2, e3);
            int t = j >> 1, o = (j & 1) * 2;
            ph[t][o]   = packf16(e0, e1);
            ph[t][o+1] = packf16(e2, e3);
        }
        // O-phase: P (single fp16) x (Vh + Vl) fp16 = 8 MMAs per jd
        #pragma unroll
        for (int jd = 0; jd < 8; jd++) {
            uint32_t vb[8], vbl[8];
            #pragma unroll
            for (int tp = 0; tp < 2; tp++) {
                uint32_t ahv = vhb + (uint32_t)(32*tp)*144 + voff + (uint32_t)jd*16;
                uint32_t alv = vlb + (uint32_t)(32*tp)*144 + voff + (uint32_t)jd*16;
                ldsm4t(vb[4*tp+0],  vb[4*tp+1],  vb[4*tp+2],  vb[4*tp+3],  ahv);
                ldsm4t(vbl[4*tp+0], vbl[4*tp+1], vbl[4*tp+2], vbl[4*tp+3], alv);
            }
            #pragma unroll
            for (int t = 0; t < 4; t++) {
                mma16816f(oacc[jd], ph[t], vb[2*t],  vb[2*t+1]);
                mma16816f(oacc[jd], ph[t], vbl[2*t], vbl[2*t+1]);
            }
        }
    }

    rs0 += __shfl_xor_sync(0xffffffffu, rs0, 1);
    rs0 += __shfl_xor_sync(0xffffffffu, rs0, 2);
    rs1 += __shfl_xor_sync(0xffffffffu, rs1, 1);
    rs1 += __shfl_xor_sync(0xffffffffu, rs1, 2);
    const float rinv0 = 1.f / rs0, rinv1 = 1.f / rs1;
    if (cc == 0) {
        s_rinv[16*w + g]     = rinv0;
        s_rinv[16*w + g + 8] = rinv1;
    }

    // O epilogue (bf16 hi/lo for outproj)
    #pragma unroll
    for (int jd = 0; jd < 8; jd++) {
        int col = 8*jd + 2*cc;
        uint32_t hp, lp;
        packsplit(oacc[jd][0]*rinv0, oacc[jd][1]*rinv0, hp, lp);
        size_t i0 = ((size_t)bh*L + r0)*64 + col;
        *(uint32_t*)(g_aoh + i0) = hp; *(uint32_t*)(g_aol + i0) = lp;
        packsplit(oacc[jd][2]*rinv1, oacc[jd][3]*rinv1, hp, lp);
        size_t i1 = ((size_t)bh*L + r1)*64 + col;
        *(uint32_t*)(g_aoh + i1) = hp; *(uint32_t*)(g_aol + i1) = lp;
    }
    __syncthreads();

    // ---- fused normalization: rescale this CTA's 128 x 4096 wout slab ------
    // Fully coalesced float4 traffic; overlaps with other CTAs' MMA phases.
    {
        float* wb = wout + ((size_t)bh*L + q0) * (size_t)L;
        #pragma unroll 4
        for (int i = tid; i < 128*1024; i += 256) {
            int row = i >> 10;
            int c4  = (i & 1023) << 2;
            float rv = s_rinv[row];
            float4 v = *(float4*)(wb + (size_t)row*L + c4);
            v.x *= rv; v.y *= rv; v.z *= rv; v.w *= rv;
            *(float4*)(wb + (size_t)row*L + c4) = v;
        }
    }
}

// ---------------- output projection via mma.sync bf16x3 --------------------
#define OP_AH 0
#define OP_AL 18432
#define OP_BH 36864
#define OP_BL 46080
#define OP_SZ 55296

__global__ void __launch_bounds__(256) outproj_mma(float* __restrict__ out) {
    extern __shared__ char smem[];
    const uint32_t sb = su32(smem);
    const int tid = threadIdx.x;
    const int w = tid >> 5, l = tid & 31;
    const int g = l >> 2, cc = l & 3;
    const int m0 = blockIdx.x * 128;
    const int n0 = blockIdx.y * 64;

    const int aarr = tid >> 7, arow = tid & 127;
    const int am = m0 + arow, ab = am >> 12, al_ = am & 4095;
    const unsigned short* asrc0 = (aarr ? g_aol : g_aoh);
    const uint32_t adst = sb + (aarr ? OP_AL : OP_AH) + arow*144;
    const int barr = tid >> 7, brow = (tid >> 1) & 63, bseg0 = (tid & 1) * 4;
    const unsigned short* bsrc = (barr ? g_wl : g_wh) + (size_t)3*262144 + (size_t)(n0 + brow)*512;
    const uint32_t bdst = sb + (barr ? OP_BL : OP_BH) + brow*144;

    float c[8][4] = {};
    for (int kt = 0; kt < 8; kt++) {
        const unsigned short* as = asrc0 + ((size_t)(ab*H + kt)*L + al_)*64;
        #pragma unroll
        for (int sgi = 0; sgi < 8; sgi++) cpa16(adst + sgi*16, as + sgi*8);
        #pragma unroll
        for (int i = 0; i < 4; i++) {
            int seg = bseg0 + i;
            cpa16(bdst + seg*16, bsrc + kt*64 + seg*8);
        }
        CPCOMMIT();
        CPWAIT0();
        __syncthreads();

        uint32_t ah[4][4], alr[4][4];
        const uint32_t aoff = (uint32_t)((l & 15) + 16*w) * 144 + (uint32_t)(l >> 4) * 16;
        #pragma unroll
        for (int ks = 0; ks < 4; ks++) {
            ldsm4(ah[ks][0],  ah[ks][1],  ah[ks][2],  ah[ks][3],  sb + OP_AH + aoff + ks*32);
            ldsm4(alr[ks][0], alr[ks][1], alr[ks][2], alr[ks][3], sb + OP_AL + aoff + ks*32);
        }
        const uint32_t boff = (uint32_t)(l & 7) * 144 + (uint32_t)(l >> 3) * 16;
        #pragma unroll
        for (int j = 0; j < 8; j++) {
            uint32_t kb[8], kbl[8];
            uint32_t bh_ = sb + OP_BH + (uint32_t)(8*j)*144 + boff;
            uint32_t bl_ = sb + OP_BL + (uint32_t)(8*j)*144 + boff;
            ldsm4(kb[0], kb[1], kb[2], kb[3], bh_);
            ldsm4(kb[4], kb[5], kb[6], kb[7], bh_ + 64);
            ldsm4(kbl[0], kbl[1], kbl[2], kbl[3], bl_);
            ldsm4(kbl[4], kbl[5], kbl[6], kbl[7], bl_ + 64);
            #pragma unroll
            for (int ks = 0; ks < 4; ks++) {
                mma16816(c[j], ah[ks],  kb[2*ks],  kb[2*ks+1]);
                mma16816(c[j], ah[ks],  kbl[2*ks], kbl[2*ks+1]);
                mma16816(c[j], alr[ks], kb[2*ks],  kb[2*ks+1]);
            }
        }
        __syncthreads();
    }

    const int r0 = m0 + 16*w + g, r1 = r0 + 8;
    #pragma unroll
    for (int j = 0; j < 8; j++) {
        int col = 8*j + 2*cc;
        float bia0 = g_wb[3*512 + n0 + col], bia1 = g_wb[3*512 + n0 + col + 1];
        *(float2*)(out + (size_t)r0*512 + n0 + col) = make_float2(c[j][0] + bia0, c[j][1] + bia1);
        *(float2*)(out + (size_t)r1*512 + n0 + col) = make_float2(c[j][2] + bia0, c[j][3] + bia1);
    }
}

extern "C" void kernel_launch(void* const* d_in, const int* in_sizes, int n_in,
                              void* d_out, int out_size) {
    const float* q    = (const float*)d_in[0];
    const float* k    = (const float*)d_in[1];
    const float* v    = (const float*)d_in[2];
    const int*   mask = (const int*)d_in[3];
    const float* Wq   = (const float*)d_in[4];
    const float* bq   = (const float*)d_in[5];
    const float* Wk   = (const float*)d_in[6];
    const float* bk   = (const float*)d_in[7];
    const float* Wv   = (const float*)d_in[8];
    const float* bv   = (const float*)d_in[9];
    const float* Wo   = (const float*)d_in[10];
    const float* bo   = (const float*)d_in[11];

    float* out  = (float*)d_out;                    // (N, L, 512)
    float* wout = out + (size_t)NB*L*D;             // (N, H, L, L)

    cudaFuncSetAttribute(proj_mma,    cudaFuncAttributeMaxDynamicSharedMemorySize, PJ_SZ);
    cudaFuncSetAttribute(attn_mma,    cudaFuncAttributeMaxDynamicSharedMemorySize, 2*AT_BUF);
    cudaFuncSetAttribute(outproj_mma, cudaFuncAttributeMaxDynamicSharedMemorySize, OP_SZ);

    mask_scan  <<<NB*L, 256>>>(mask);
    prep_w     <<<4096, 256>>>(Wq, Wk, Wv, Wo, bq, bk, bv, bo);
    proj_mma   <<<dim3(64,8,3), 256, PJ_SZ>>>(q, k, v);
    attn_mma   <<<dim3(32,8,2), 256, 2*AT_BUF>>>(mask, wout);
    outproj_mma<<<dim3(64,8),   256, OP_SZ>>>(out);
}

// round 14
// speedup vs baseline: 1.2031x; 1.2031x over previous
#include <cuda_runtime.h>
#include <cuda_bf16.h>
#include <cstdint>

#define NB 2
#define L  4096
#define D  512
#define H  8
#define DH 64

#define SCALE 0.18033688011111793f  /* log2(e)/8 */

__device__ unsigned short g_qh[NB*H*L*DH], g_ql[NB*H*L*DH];
__device__ unsigned short g_kh[NB*H*L*DH], g_kl[NB*H*L*DH];
__device__ unsigned short g_vh[NB*H*L*DH], g_vl[NB*H*L*DH];   // fp16 hi/lo
__device__ unsigned short g_aoh[NB*H*L*DH], g_aol[NB*H*L*DH];
__device__ unsigned short g_wh[4*D*D], g_wl[4*D*D];
__device__ float g_wb[4*D];
__device__ float g_rowsum[NB*H*L];
__device__ int   g_allones[NB*L];
__device__ unsigned short g_p[(size_t)NB*H*L*L];   // fp16 unnormalized P (1.07GB)

// ------------------------------ helpers ------------------------------------
__device__ __forceinline__ uint32_t su32(const void* p) {
    uint32_t a;
    asm("{ .reg .u64 t; cvta.to.shared.u64 t, %1; cvt.u32.u64 %0, t; }" : "=r"(a) : "l"(p));
    return a;
}
__device__ __forceinline__ float ex2(float x) {
    float r; asm("ex2.approx.f32 %0, %1;" : "=f"(r) : "f"(x)); return r;
}
__device__ __forceinline__ void packsplit(float f0, float f1, uint32_t& hp, uint32_t& lp) {
    asm("cvt.rn.bf16x2.f32 %0, %1, %2;" : "=r"(hp) : "f"(f1), "f"(f0));
    float r0 = __uint_as_float(hp << 16);
    float r1 = __uint_as_float(hp & 0xffff0000u);
    float l0 = f0 - r0, l1 = f1 - r1;
    asm("cvt.rn.bf16x2.f32 %0, %1, %2;" : "=r"(lp) : "f"(l1), "f"(l0));
}
__device__ __forceinline__ uint32_t packf16(float f0, float f1) {
    uint32_t r;
    asm("cvt.rn.f16x2.f32 %0, %1, %2;" : "=r"(r) : "f"(f1), "f"(f0));
    return r;
}
__device__ __forceinline__ void packsplit_f16(float f0, float f1, uint32_t& hp, uint32_t& lp) {
    asm("cvt.rn.f16x2.f32 %0, %1, %2;" : "=r"(hp) : "f"(f1), "f"(f0));
    float r0, r1;
    asm("{ .reg .b16 lo, hi; mov.b32 {lo, hi}, %2; cvt.f32.f16 %0, lo; cvt.f32.f16 %1, hi; }"
        : "=f"(r0), "=f"(r1) : "r"(hp));
    asm("cvt.rn.f16x2.f32 %0, %1, %2;" : "=r"(lp) : "f"(f1 - r1), "f"(f0 - r0));
}
__device__ __forceinline__ void unpackf16(uint32_t p, float& f0, float& f1) {
    asm("{ .reg .b16 a,b; mov.b32 {a,b}, %2; cvt.f32.f16 %0, a; cvt.f32.f16 %1, b; }"
        : "=f"(f0), "=f"(f1) : "r"(p));
}
__device__ __forceinline__ void ldsm4(uint32_t& r0, uint32_t& r1, uint32_t& r2, uint32_t& r3, uint32_t a) {
    asm volatile("ldmatrix.sync.aligned.m8n8.x4.shared.b16 {%0,%1,%2,%3}, [%4];"
        : "=r"(r0), "=r"(r1), "=r"(r2), "=r"(r3) : "r"(a));
}
__device__ __forceinline__ void ldsm4t(uint32_t& r0, uint32_t& r1, uint32_t& r2, uint32_t& r3, uint32_t a) {
    asm volatile("ldmatrix.sync.aligned.m8n8.x4.trans.shared.b16 {%0,%1,%2,%3}, [%4];"
        : "=r"(r0), "=r"(r1), "=r"(r2), "=r"(r3) : "r"(a));
}
__device__ __forceinline__ void mma16816(float c[4], const uint32_t a[4], uint32_t b0, uint32_t b1) {
    asm volatile("mma.sync.aligned.m16n8k16.row.col.f32.bf16.bf16.f32 "
        "{%0,%1,%2,%3},{%4,%5,%6,%7},{%8,%9},{%0,%1,%2,%3};"
        : "+f"(c[0]), "+f"(c[1]), "+f"(c[2]), "+f"(c[3])
        : "r"(a[0]), "r"(a[1]), "r"(a[2]), "r"(a[3]), "r"(b0), "r"(b1));
}
__device__ __forceinline__ void mma16816f(float c[4], const uint32_t a[4], uint32_t b0, uint32_t b1) {
    asm volatile("mma.sync.aligned.m16n8k16.row.col.f32.f16.f16.f32 "
        "{%0,%1,%2,%3},{%4,%5,%6,%7},{%8,%9},{%0,%1,%2,%3};"
        : "+f"(c[0]), "+f"(c[1]), "+f"(c[2]), "+f"(c[3])
        : "r"(a[0]), "r"(a[1]), "r"(a[2]), "r"(a[3]), "r"(b0), "r"(b1));
}
__device__ __forceinline__ void cpa16(uint32_t dst, const void* src) {
    asm volatile("cp.async.cg.shared.global [%0], [%1], 16;"
        :: "r"(dst), "l"(__cvta_generic_to_global(src)));
}
#define CPCOMMIT() asm volatile("cp.async.commit_group;" ::: "memory")
#define CPWAIT0()  asm volatile("cp.async.wait_group 0;" ::: "memory")

// ------------------------------ mask pre-scan ------------------------------
__global__ void mask_scan(const int* __restrict__ mask) {
    int row = blockIdx.x;
    const int4* m = (const int4*)(mask + (size_t)row * L);
    int ok = 1;
    for (int i = threadIdx.x; i < L/4; i += 256) {
        int4 v = m[i];
        ok &= (v.x != 0) & (v.y != 0) & (v.z != 0) & (v.w != 0);
    }
    ok = __syncthreads_and(ok);
    if (threadIdx.x == 0) g_allones[row] = ok;
}

// --------------------- weight prep: bf16 hi/lo split ------------------------
__global__ void prep_w(const float* __restrict__ Wq, const float* __restrict__ Wk,
                       const float* __restrict__ Wv, const float* __restrict__ Wo,
                       const float* __restrict__ bq, const float* __restrict__ bk,
                       const float* __restrict__ bv, const float* __restrict__ bo) {
    int idx = blockIdx.x * 256 + threadIdx.x;
    int mat = idx >> 18;
    int rem = idx & 262143;
    const float* W = (mat==0) ? Wq : (mat==1) ? Wk : (mat==2) ? Wv : Wo;
    float v = W[rem];
    if (mat == 0) v *= SCALE;
    __nv_bfloat16 hb = __float2bfloat16(v);
    float r = __bfloat162float(hb);
    __nv_bfloat16 lb = __float2bfloat16(v - r);
    g_wh[idx] = *(unsigned short*)&hb;
    g_wl[idx] = *(unsigned short*)&lb;
    if (idx < 4*D) {
        int m2 = idx >> 9, n = idx & 511;
        const float* B = (m2==0) ? bq : (m2==1) ? bk : (m2==2) ? bv : bo;
        float bvl = B[n];
        if (m2 == 0) bvl *= SCALE;
        g_wb[idx] = bvl;
    }
}

// ---------------- QKV projections via mma.sync bf16x3 -----------------------
#define PJ_XH 0
#define PJ_XL 18432
#define PJ_WH 36864
#define PJ_WL 46080
#define PJ_SZ 55296

__global__ void __launch_bounds__(256) proj_mma(const float* __restrict__ xq,
                                                const float* __restrict__ xk,
                                                const float* __restrict__ xv) {
    extern __shared__ char smem[];
    const uint32_t sb = su32(smem);
    const int tid = threadIdx.x;
    const int w = tid >> 5, l = tid & 31;
    const int g = l >> 2, cc = l & 3;
    const int m0 = blockIdx.x * 128;
    const int head = blockIdx.y;
    const int z = blockIdx.z;
    const int n0 = head * 64;
    const float* X = (z==0) ? xq : (z==1) ? xk : xv;

    const int warr = tid >> 7;
    const int wrow = (tid >> 1) & 63;
    const int wseg0 = (tid & 1) * 4;
    const unsigned short* wsrc = (warr ? g_wl : g_wh) + (size_t)z*262144 + (size_t)(n0 + wrow)*512;
    const uint32_t wdst = sb + (warr ? PJ_WL : PJ_WH) + wrow*144;

    const int xrow = tid >> 1, xhalf = tid & 1;

    float c[8][4] = {};
    for (int kt = 0; kt < 8; kt++) {
        #pragma unroll
        for (int i = 0; i < 4; i++) {
            int seg = wseg0 + i;
            cpa16(wdst + seg*16, wsrc + kt*64 + seg*8);
        }
        CPCOMMIT();
        #pragma unroll
        for (int jj = 0; jj < 8; jj++) {
            int col = xhalf*32 + jj*4;
            float4 v = *(const float4*)(X + (size_t)(m0 + xrow)*512 + kt*64 + col);
            uint32_t h0,l0,h1,l1;
            packsplit(v.x, v.y, h0, l0); packsplit(v.z, v.w, h1, l1);
            *(uint2*)(smem + PJ_XH + xrow*144 + col*2) = make_uint2(h0, h1);
            *(uint2*)(smem + PJ_XL + xrow*144 + col*2) = make_uint2(l0, l1);
        }
        CPWAIT0();
        __syncthreads();

        uint32_t ah[4][4], al[4][4];
        const uint32_t aoff = (uint32_t)((l & 15) + 16*w) * 144 + (uint32_t)(l >> 4) * 16;
        #pragma unroll
        for (int ks = 0; ks < 4; ks++) {
            ldsm4(ah[ks][0], ah[ks][1], ah[ks][2], ah[ks][3], sb + PJ_XH + aoff + ks*32);
            ldsm4(al[ks][0], al[ks][1], al[ks][2], al[ks][3], sb + PJ_XL + aoff + ks*32);
        }
        const uint32_t boff = (uint32_t)(l & 7) * 144 + (uint32_t)(l >> 3) * 16;
        #pragma unroll
        for (int j = 0; j < 8; j++) {
            uint32_t kb[8], kbl[8];
            uint32_t bh_ = sb + PJ_WH + (uint32_t)(8*j)*144 + boff;
            uint32_t bl_ = sb + PJ_WL + (uint32_t)(8*j)*144 + boff;
            ldsm4(kb[0], kb[1], kb[2], kb[3], bh_);
            ldsm4(kb[4], kb[5], kb[6], kb[7], bh_ + 64);
            ldsm4(kbl[0], kbl[1], kbl[2], kbl[3], bl_);
            ldsm4(kbl[4], kbl[5], kbl[6], kbl[7], bl_ + 64);
            #pragma unroll
            for (int ks = 0; ks < 4; ks++) {
                mma16816(c[j], ah[ks], kb[2*ks],  kb[2*ks+1]);
                mma16816(c[j], ah[ks], kbl[2*ks], kbl[2*ks+1]);
                mma16816(c[j], al[ks], kb[2*ks],  kb[2*ks+1]);
            }
        }
        __syncthreads();
    }

    unsigned short* oh = (z==0) ? g_qh : (z==1) ? g_kh : g_vh;
    unsigned short* ol = (z==0) ? g_ql : (z==1) ? g_kl : g_vl;
    const int r0 = m0 + 16*w + g, r1 = r0 + 8;
    const int b0_ = r0 >> 12, l0_ = r0 & 4095;
    const int b1_ = r1 >> 12, l1_ = r1 & 4095;
    #pragma unroll
    for (int j = 0; j < 8; j++) {
        int col = 8*j + 2*cc;
        float bia0 = g_wb[z*512 + n0 + col], bia1 = g_wb[z*512 + n0 + col + 1];
        float v0a = c[j][0] + bia0, v1a = c[j][1] + bia1;
        float v0b = c[j][2] + bia0, v1b = c[j][3] + bia1;
        uint32_t hp, lp;
        if (z == 2) packsplit_f16(v0a, v1a, hp, lp);
        else        packsplit(v0a, v1a, hp, lp);
        size_t i0 = ((size_t)(b0_*H + head)*L + l0_)*64 + col;
        *(uint32_t*)(oh + i0) = hp; *(uint32_t*)(ol + i0) = lp;
        if (z == 2) packsplit_f16(v0b, v1b, hp, lp);
        else        packsplit(v0b, v1b, hp, lp);
        size_t i1 = ((size_t)(b1_*H + head)*L + l1_)*64 + col;
        *(uint32_t*)(oh + i1) = hp; *(uint32_t*)(ol + i1) = lp;
    }
}

// ---- attention (R11 base): S bf16x3, PV fp16; P stored fp16 to scratch -----
#define AT_BUF 36864   /* 4 arrays x 64 rows x 144B per buffer */

__global__ void __launch_bounds__(256) attn_mma(const int* __restrict__ mask) {
    extern __shared__ char smem[];
    const uint32_t sb = su32(smem);
    const int tid = threadIdx.x;
    const int w = tid >> 5, l = tid & 31;
    const int g = l >> 2, cc = l & 3;
    const int qt = blockIdx.x, h = blockIdx.y, b = blockIdx.z;
    const int bh = b*H + h;
    const int q0 = qt * 128;
    const int r0 = q0 + 16*w + g, r1 = r0 + 8;

    uint32_t qh[4][4], ql[4][4];
    #pragma unroll
    for (int ks = 0; ks < 4; ks++) {
        int cA = 16*ks + 2*cc;
        size_t i00 = ((size_t)bh*L + r0)*64 + cA;
        size_t i10 = ((size_t)bh*L + r1)*64 + cA;
        qh[ks][0] = *(const uint32_t*)(g_qh + i00);
        qh[ks][1] = *(const uint32_t*)(g_qh + i10);
        qh[ks][2] = *(const uint32_t*)(g_qh + i00 + 8);
        qh[ks][3] = *(const uint32_t*)(g_qh + i10 + 8);
        ql[ks][0] = *(const uint32_t*)(g_ql + i00);
        ql[ks][1] = *(const uint32_t*)(g_ql + i10);
        ql[ks][2] = *(const uint32_t*)(g_ql + i00 + 8);
        ql[ks][3] = *(const uint32_t*)(g_ql + i10 + 8);
    }
    const bool ok0 = g_allones[(size_t)b*L + r0] != 0;
    const bool ok1 = g_allones[(size_t)b*L + r1] != 0;
    const int* mrow0 = mask + ((size_t)b*L + r0) * (size_t)L;
    const int* mrow1 = mask + ((size_t)b*L + r1) * (size_t)L;

    const int sarr = tid >> 6;          // 0 kh, 1 kl, 2 vh, 3 vl
    const int srow = tid & 63;
    const unsigned short* sbase = (sarr==0) ? g_kh : (sarr==1) ? g_kl : (sarr==2) ? g_vh : g_vl;
    const unsigned short* ssrc = sbase + ((size_t)bh*L + srow)*64;
    const uint32_t sdst = sb + sarr*9216 + srow*144;

    const uint32_t koff = (uint32_t)(l & 7) * 144 + (uint32_t)(l >> 3) * 16;
    const uint32_t voff = (uint32_t)((l & 7) + 8*(l >> 3)) * 144;

    unsigned short* p0 = g_p + ((size_t)bh*L + r0) * (size_t)L;
    unsigned short* p1 = g_p + ((size_t)bh*L + r1) * (size_t)L;

    float oacc[8][4] = {};
    float rs0 = 0.f, rs1 = 0.f;

    // prologue: stage k-tile 0 into buffer 0
    #pragma unroll
    for (int sgi = 0; sgi < 8; sgi++) cpa16(sdst + sgi*16, ssrc + sgi*8);
    CPCOMMIT();

    for (int it = 0; it < 64; it++) {
        const int kc = it * 64;
        CPWAIT0();
        __syncthreads();
        if (it + 1 < 64) {
            const int nb_ = (it + 1) & 1;
            const unsigned short* s2 = ssrc + (size_t)(kc + 64)*64;
            #pragma unroll
            for (int sgi = 0; sgi < 8; sgi++) cpa16(sdst + nb_*AT_BUF + sgi*16, s2 + sgi*8);
            CPCOMMIT();
        }
        const uint32_t bufb = sb + (it & 1)*AT_BUF;
        const uint32_t khb = bufb, klb = bufb + 9216, vhb = bufb + 18432, vlb = bufb + 27648;

        uint32_t ph[4][4];
        #pragma unroll
        for (int j = 0; j < 8; j++) {
            uint32_t kb[8], kbl[8];
            uint32_t ah = khb + (uint32_t)(8*j)*144 + koff;
            uint32_t al = klb + (uint32_t)(8*j)*144 + koff;
            ldsm4(kb[0], kb[1], kb[2], kb[3], ah);
            ldsm4(kb[4], kb[5], kb[6], kb[7], ah + 64);
            ldsm4(kbl[0], kbl[1], kbl[2], kbl[3], al);
            ldsm4(kbl[4], kbl[5], kbl[6], kbl[7], al + 64);
            float sacc[4] = {0.f, 0.f, 0.f, 0.f};
            #pragma unroll
            for (int ks = 0; ks < 4; ks++) {
                mma16816(sacc, qh[ks], kb[2*ks],  kb[2*ks+1]);
                mma16816(sacc, qh[ks], kbl[2*ks], kbl[2*ks+1]);
                mma16816(sacc, ql[ks], kb[2*ks],  kb[2*ks+1]);
            }
            float e0 = ex2(sacc[0]), e1 = ex2(sacc[1]);
            float e2 = ex2(sacc[2]), e3 = ex2(sacc[3]);
            int col = kc + 8*j + 2*cc;
            if (!ok0) {
                if (!mrow0[col])   e0 = 0.f;
                if (!mrow0[col+1]) e1 = 0.f;
            }
            if (!ok1) {
                if (!mrow1[col])   e2 = 0.f;
                if (!mrow1[col+1]) e3 = 0.f;
            }
            rs0 += e0 + e1; rs1 += e2 + e3;
            int t = j >> 1, o = (j & 1) * 2;
            uint32_t pk0 = packf16(e0, e1);
            uint32_t pk1 = packf16(e2, e3);
            ph[t][o]   = pk0;
            ph[t][o+1] = pk1;
            *(uint32_t*)(p0 + col) = pk0;       // unnormalized fp16 P
            *(uint32_t*)(p1 + col) = pk1;
        }
        // O-phase: P (single fp16) x (Vh + Vl) fp16 = 8 MMAs per jd
        #pragma unroll
        for (int jd = 0; jd < 8; jd++) {
            uint32_t vb[8], vbl[8];
            #pragma unroll
            for (int tp = 0; tp < 2; tp++) {
                uint32_t ahv = vhb + (uint32_t)(32*tp)*144 + voff + (uint32_t)jd*16;
                uint32_t alv = vlb + (uint32_t)(32*tp)*144 + voff + (uint32_t)jd*16;
                ldsm4t(vb[4*tp+0],  vb[4*tp+1],  vb[4*tp+2],  vb[4*tp+3],  ahv);
                ldsm4t(vbl[4*tp+0], vbl[4*tp+1], vbl[4*tp+2], vbl[4*tp+3], alv);
            }
            #pragma unroll
            for (int t = 0; t < 4; t++) {
                mma16816f(oacc[jd], ph[t], vb[2*t],  vb[2*t+1]);
                mma16816f(oacc[jd], ph[t], vbl[2*t], vbl[2*t+1]);
            }
        }
    }

    rs0 += __shfl_xor_sync(0xffffffffu, rs0, 1);
    rs0 += __shfl_xor_sync(0xffffffffu, rs0, 2);
    rs1 += __shfl_xor_sync(0xffffffffu, rs1, 1);
    rs1 += __shfl_xor_sync(0xffffffffu, rs1, 2);
    if (cc == 0) {
        g_rowsum[(size_t)bh*L + r0] = rs0;
        g_rowsum[(size_t)bh*L + r1] = rs1;
    }
    const float rinv0 = 1.f / rs0, rinv1 = 1.f / rs1;

    #pragma unroll
    for (int jd = 0; jd < 8; jd++) {
        int col = 8*jd + 2*cc;
        uint32_t hp, lp;
        packsplit(oacc[jd][0]*rinv0, oacc[jd][1]*rinv0, hp, lp);
        size_t i0 = ((size_t)bh*L + r0)*64 + col;
        *(uint32_t*)(g_aoh + i0) = hp; *(uint32_t*)(g_aol + i0) = lp;
        packsplit(oacc[jd][2]*rinv1, oacc[jd][3]*rinv1, hp, lp);
        size_t i1 = ((size_t)bh*L + r1)*64 + col;
        *(uint32_t*)(g_aoh + i1) = hp; *(uint32_t*)(g_aol + i1) = lp;
    }
}

// ---- fused tail: blocks [0,512) outproj, blocks [512, 512+65536) normalize -
#define OP_AH 0
#define OP_AL 18432
#define OP_BH 36864
#define OP_BL 46080
#define OP_SZ 55296

__global__ void __launch_bounds__(256) tail_kernel(float* __restrict__ out,
                                                   float* __restrict__ wout) {
    const int bi = blockIdx.x;
    const int tid = threadIdx.x;
    if (bi >= 512) {
        // --------- normalize: one wout row per block, fp16 P -> fp32 --------
        const int row = bi - 512;                  // 0 .. NB*H*L-1
        const float rinv = 1.f / g_rowsum[row];
        const uint2* src = (const uint2*)(g_p + (size_t)row * L);
        float4* dst = (float4*)(wout + (size_t)row * L);
        #pragma unroll
        for (int i = 0; i < 4; i++) {
            int idx = i*256 + tid;
            uint2 pv = src[idx];
            float f0, f1, f2, f3;
            unpackf16(pv.x, f0, f1);
            unpackf16(pv.y, f2, f3);
            dst[idx] = make_float4(f0*rinv, f1*rinv, f2*rinv, f3*rinv);
        }
        return;
    }
    // ----------------------- outproj (mma.sync bf16x3) ----------------------
    extern __shared__ char smem[];
    const uint32_t sb = su32(smem);
    const int w = tid >> 5, l = tid & 31;
    const int g = l >> 2, cc = l & 3;
    const int m0 = (bi >> 3) * 128;
    const int n0 = (bi & 7) * 64;

    const int aarr = tid >> 7, arow = tid & 127;
    const int am = m0 + arow, ab = am >> 12, al_ = am & 4095;
    const unsigned short* asrc0 = (aarr ? g_aol : g_aoh);
    const uint32_t adst = sb + (aarr ? OP_AL : OP_AH) + arow*144;
    const int barr = tid >> 7, brow = (tid >> 1) & 63, bseg0 = (tid & 1) * 4;
    const unsigned short* bsrc = (barr ? g_wl : g_wh) + (size_t)3*262144 + (size_t)(n0 + brow)*512;
    const uint32_t bdst = sb + (barr ? OP_BL : OP_BH) + brow*144;

    float c[8][4] = {};
    for (int kt = 0; kt < 8; kt++) {
        const unsigned short* as = asrc0 + ((size_t)(ab*H + kt)*L + al_)*64;
        #pragma unroll
        for (int sgi = 0; sgi < 8; sgi++) cpa16(adst + sgi*16, as + sgi*8);
        #pragma unroll
        for (int i = 0; i < 4; i++) {
            int seg = bseg0 + i;
            cpa16(bdst + seg*16, bsrc + kt*64 + seg*8);
        }
        CPCOMMIT();
        CPWAIT0();
        __syncthreads();

        uint32_t ah[4][4], alr[4][4];
        const uint32_t aoff = (uint32_t)((l & 15) + 16*w) * 144 + (uint32_t)(l >> 4) * 16;
        #pragma unroll
        for (int ks = 0; ks < 4; ks++) {
            ldsm4(ah[ks][0],  ah[ks][1],  ah[ks][2],  ah[ks][3],  sb + OP_AH + aoff + ks*32);
            ldsm4(alr[ks][0], alr[ks][1], alr[ks][2], alr[ks][3], sb + OP_AL + aoff + ks*32);
        }
        const uint32_t boff = (uint32_t)(l & 7) * 144 + (uint32_t)(l >> 3) * 16;
        #pragma unroll
        for (int j = 0; j < 8; j++) {
            uint32_t kb[8], kbl[8];
            uint32_t bh_ = sb + OP_BH + (uint32_t)(8*j)*144 + boff;
            uint32_t bl_ = sb + OP_BL + (uint32_t)(8*j)*144 + boff;
            ldsm4(kb[0], kb[1], kb[2], kb[3], bh_);
            ldsm4(kb[4], kb[5], kb[6], kb[7], bh_ + 64);
            ldsm4(kbl[0], kbl[1], kbl[2], kbl[3], bl_);
            ldsm4(kbl[4], kbl[5], kbl[6], kbl[7], bl_ + 64);
            #pragma unroll
            for (int ks = 0; ks < 4; ks++) {
                mma16816(c[j], ah[ks],  kb[2*ks],  kb[2*ks+1]);
                mma16816(c[j], ah[ks],  kbl[2*ks], kbl[2*ks+1]);
                mma16816(c[j], alr[ks], kb[2*ks],  kb[2*ks+1]);
            }
        }
        __syncthreads();
    }

    const int r0 = m0 + 16*w + g, r1 = r0 + 8;
    #pragma unroll
    for (int j = 0; j < 8; j++) {
        int col = 8*j + 2*cc;
        float bia0 = g_wb[3*512 + n0 + col], bia1 = g_wb[3*512 + n0 + col + 1];
        *(float2*)(out + (size_t)r0*512 + n0 + col) = make_float2(c[j][0] + bia0, c[j][1] + bia1);
        *(float2*)(out + (size_t)r1*512 + n0 + col) = make_float2(c[j][2] + bia0, c[j][3] + bia1);
    }
}

extern "C" void kernel_launch(void* const* d_in, const int* in_sizes, int n_in,
                              void* d_out, int out_size) {
    const float* q    = (const float*)d_in[0];
    const float* k    = (const float*)d_in[1];
    const float* v    = (const float*)d_in[2];
    const int*   mask = (const int*)d_in[3];
    const float* Wq   = (const float*)d_in[4];
    const float* bq   = (const float*)d_in[5];
    const float* Wk   = (const float*)d_in[6];
    const float* bk   = (const float*)d_in[7];
    const float* Wv   = (const float*)d_in[8];
    const float* bv   = (const float*)d_in[9];
    const float* Wo   = (const float*)d_in[10];
    const float* bo   = (const float*)d_in[11];

    float* out  = (float*)d_out;                    // (N, L, 512)
    float* wout = out + (size_t)NB*L*D;             // (N, H, L, L)

    cudaFuncSetAttribute(proj_mma,    cudaFuncAttributeMaxDynamicSharedMemorySize, PJ_SZ);
    cudaFuncSetAttribute(attn_mma,    cudaFuncAttributeMaxDynamicSharedMemorySize, 2*AT_BUF);
    cudaFuncSetAttribute(tail_kernel, cudaFuncAttributeMaxDynamicSharedMemorySize, OP_SZ);

    mask_scan  <<<NB*L, 256>>>(mask);
    prep_w     <<<4096, 256>>>(Wq, Wk, Wv, Wo, bq, bk, bv, bo);
    proj_mma   <<<dim3(64,8,3), 256, PJ_SZ>>>(q, k, v);
    attn_mma   <<<dim3(32,8,2), 256, 2*AT_BUF>>>(mask);
    tail_kernel<<<512 + NB*H*L, 256, OP_SZ>>>(out, wout);
}

// round 15
// speedup vs baseline: 1.5378x; 1.2782x over previous
#include <cuda_runtime.h>
#include <cuda_bf16.h>
#include <cstdint>

#define NB 2
#define L  4096
#define D  512
#define H  8
#define DH 64

#define SCALE 0.18033688011111793f  /* log2(e)/8 */

__device__ unsigned short g_qh[NB*H*L*DH], g_ql[NB*H*L*DH];
__device__ unsigned short g_kh[NB*H*L*DH], g_kl[NB*H*L*DH];
__device__ unsigned short g_vh[NB*H*L*DH], g_vl[NB*H*L*DH];   // fp16 hi/lo
__device__ unsigned short g_aoh[NB*H*L*DH], g_aol[NB*H*L*DH];
__device__ unsigned short g_wh[4*D*D], g_wl[4*D*D];
__device__ float g_wb[4*D];
__device__ float g_rowsum[NB*H*L];
__device__ int   g_allones[NB*L];
__device__ unsigned short g_p[(size_t)NB*H*L*L];   // fp16 unnormalized P

// ------------------------------ helpers ------------------------------------
__device__ __forceinline__ uint32_t su32(const void* p) {
    uint32_t a;
    asm("{ .reg .u64 t; cvta.to.shared.u64 t, %1; cvt.u32.u64 %0, t; }" : "=r"(a) : "l"(p));
    return a;
}
__device__ __forceinline__ float ex2(float x) {
    float r; asm("ex2.approx.f32 %0, %1;" : "=f"(r) : "f"(x)); return r;
}
__device__ __forceinline__ void packsplit(float f0, float f1, uint32_t& hp, uint32_t& lp) {
    asm("cvt.rn.bf16x2.f32 %0, %1, %2;" : "=r"(hp) : "f"(f1), "f"(f0));
    float r0 = __uint_as_float(hp << 16);
    float r1 = __uint_as_float(hp & 0xffff0000u);
    float l0 = f0 - r0, l1 = f1 - r1;
    asm("cvt.rn.bf16x2.f32 %0, %1, %2;" : "=r"(lp) : "f"(l1), "f"(l0));
}
__device__ __forceinline__ uint32_t packf16(float f0, float f1) {
    uint32_t r;
    asm("cvt.rn.f16x2.f32 %0, %1, %2;" : "=r"(r) : "f"(f1), "f"(f0));
    return r;
}
__device__ __forceinline__ void packsplit_f16(float f0, float f1, uint32_t& hp, uint32_t& lp) {
    asm("cvt.rn.f16x2.f32 %0, %1, %2;" : "=r"(hp) : "f"(f1), "f"(f0));
    float r0, r1;
    asm("{ .reg .b16 lo, hi; mov.b32 {lo, hi}, %2; cvt.f32.f16 %0, lo; cvt.f32.f16 %1, hi; }"
        : "=f"(r0), "=f"(r1) : "r"(hp));
    asm("cvt.rn.f16x2.f32 %0, %1, %2;" : "=r"(lp) : "f"(f1 - r1), "f"(f0 - r0));
}
__device__ __forceinline__ void unpackf16(uint32_t p, float& f0, float& f1) {
    asm("{ .reg .b16 a,b; mov.b32 {a,b}, %2; cvt.f32.f16 %0, a; cvt.f32.f16 %1, b; }"
        : "=f"(f0), "=f"(f1) : "r"(p));
}
__device__ __forceinline__ void ldsm4(uint32_t& r0, uint32_t& r1, uint32_t& r2, uint32_t& r3, uint32_t a) {
    asm volatile("ldmatrix.sync.aligned.m8n8.x4.shared.b16 {%0,%1,%2,%3}, [%4];"
        : "=r"(r0), "=r"(r1), "=r"(r2), "=r"(r3) : "r"(a));
}
__device__ __forceinline__ void ldsm4t(uint32_t& r0, uint32_t& r1, uint32_t& r2, uint32_t& r3, uint32_t a) {
    asm volatile("ldmatrix.sync.aligned.m8n8.x4.trans.shared.b16 {%0,%1,%2,%3}, [%4];"
        : "=r"(r0), "=r"(r1), "=r"(r2), "=r"(r3) : "r"(a));
}
__device__ __forceinline__ void mma16816(float c[4], const uint32_t a[4], uint32_t b0, uint32_t b1) {
    asm volatile("mma.sync.aligned.m16n8k16.row.col.f32.bf16.bf16.f32 "
        "{%0,%1,%2,%3},{%4,%5,%6,%7},{%8,%9},{%0,%1,%2,%3};"
        : "+f"(c[0]), "+f"(c[1]), "+f"(c[2]), "+f"(c[3])
        : "r"(a[0]), "r"(a[1]), "r"(a[2]), "r"(a[3]), "r"(b0), "r"(b1));
}
__device__ __forceinline__ void mma16816f(float c[4], const uint32_t a[4], uint32_t b0, uint32_t b1) {
    asm volatile("mma.sync.aligned.m16n8k16.row.col.f32.f16.f16.f32 "
        "{%0,%1,%2,%3},{%4,%5,%6,%7},{%8,%9},{%0,%1,%2,%3};"
        : "+f"(c[0]), "+f"(c[1]), "+f"(c[2]), "+f"(c[3])
        : "r"(a[0]), "r"(a[1]), "r"(a[2]), "r"(a[3]), "r"(b0), "r"(b1));
}
__device__ __forceinline__ void cpa16(uint32_t dst, const void* src) {
    asm volatile("cp.async.cg.shared.global [%0], [%1], 16;"
        :: "r"(dst), "l"(__cvta_generic_to_global(src)));
}
#define CPCOMMIT() asm volatile("cp.async.commit_group;" ::: "memory")
#define CPWAIT0()  asm volatile("cp.async.wait_group 0;" ::: "memory")

// ------------------------------ mask pre-scan ------------------------------
__global__ void mask_scan(const int* __restrict__ mask) {
    int row = blockIdx.x;
    const int4* m = (const int4*)(mask + (size_t)row * L);
    int ok = 1;
    for (int i = threadIdx.x; i < L/4; i += 256) {
        int4 v = m[i];
        ok &= (v.x != 0) & (v.y != 0) & (v.z != 0) & (v.w != 0);
    }
    ok = __syncthreads_and(ok);
    if (threadIdx.x == 0) g_allones[row] = ok;
}

// --------------------- weight prep: bf16 hi/lo split ------------------------
__global__ void prep_w(const float* __restrict__ Wq, const float* __restrict__ Wk,
                       const float* __restrict__ Wv, const float* __restrict__ Wo,
                       const float* __restrict__ bq, const float* __restrict__ bk,
                       const float* __restrict__ bv, const float* __restrict__ bo) {
    int idx = blockIdx.x * 256 + threadIdx.x;
    int mat = idx >> 18;
    int rem = idx & 262143;
    const float* W = (mat==0) ? Wq : (mat==1) ? Wk : (mat==2) ? Wv : Wo;
    float v = W[rem];
    if (mat == 0) v *= SCALE;
    __nv_bfloat16 hb = __float2bfloat16(v);
    float r = __bfloat162float(hb);
    __nv_bfloat16 lb = __float2bfloat16(v - r);
    g_wh[idx] = *(unsigned short*)&hb;
    g_wl[idx] = *(unsigned short*)&lb;
    if (idx < 4*D) {
        int m2 = idx >> 9, n = idx & 511;
        const float* B = (m2==0) ? bq : (m2==1) ? bk : (m2==2) ? bv : bo;
        float bvl = B[n];
        if (m2 == 0) bvl *= SCALE;
        g_wb[idx] = bvl;
    }
}

// ---------------- QKV projections via mma.sync bf16x3 -----------------------
#define PJ_XH 0
#define PJ_XL 18432
#define PJ_WH 36864
#define PJ_WL 46080
#define PJ_SZ 55296

__global__ void __launch_bounds__(256) proj_mma(const float* __restrict__ xq,
                                                const float* __restrict__ xk,
                                                const float* __restrict__ xv) {
    extern __shared__ char smem[];
    const uint32_t sb = su32(smem);
    const int tid = threadIdx.x;
    const int w = tid >> 5, l = tid & 31;
    const int g = l >> 2, cc = l & 3;
    const int m0 = blockIdx.x * 128;
    const int head = blockIdx.y;
    const int z = blockIdx.z;
    const int n0 = head * 64;
    const float* X = (z==0) ? xq : (z==1) ? xk : xv;

    const int warr = tid >> 7;
    const int wrow = (tid >> 1) & 63;
    const int wseg0 = (tid & 1) * 4;
    const unsigned short* wsrc = (warr ? g_wl : g_wh) + (size_t)z*262144 + (size_t)(n0 + wrow)*512;
    const uint32_t wdst = sb + (warr ? PJ_WL : PJ_WH) + wrow*144;

    const int xrow = tid >> 1, xhalf = tid & 1;

    float c[8][4] = {};
    for (int kt = 0; kt < 8; kt++) {
        #pragma unroll
        for (int i = 0; i < 4; i++) {
            int seg = wseg0 + i;
            cpa16(wdst + seg*16, wsrc + kt*64 + seg*8);
        }
        CPCOMMIT();
        #pragma unroll
        for (int jj = 0; jj < 8; jj++) {
            int col = xhalf*32 + jj*4;
            float4 v = *(const float4*)(X + (size_t)(m0 + xrow)*512 + kt*64 + col);
            uint32_t h0,l0,h1,l1;
            packsplit(v.x, v.y, h0, l0); packsplit(v.z, v.w, h1, l1);
            *(uint2*)(smem + PJ_XH + xrow*144 + col*2) = make_uint2(h0, h1);
            *(uint2*)(smem + PJ_XL + xrow*144 + col*2) = make_uint2(l0, l1);
        }
        CPWAIT0();
        __syncthreads();

        uint32_t ah[4][4], al[4][4];
        const uint32_t aoff = (uint32_t)((l & 15) + 16*w) * 144 + (uint32_t)(l >> 4) * 16;
        #pragma unroll
        for (int ks = 0; ks < 4; ks++) {
            ldsm4(ah[ks][0], ah[ks][1], ah[ks][2], ah[ks][3], sb + PJ_XH + aoff + ks*32);
            ldsm4(al[ks][0], al[ks][1], al[ks][2], al[ks][3], sb + PJ_XL + aoff + ks*32);
        }
        const uint32_t boff = (uint32_t)(l & 7) * 144 + (uint32_t)(l >> 3) * 16;
        #pragma unroll
        for (int j = 0; j < 8; j++) {
            uint32_t kb[8], kbl[8];
            uint32_t bh_ = sb + PJ_WH + (uint32_t)(8*j)*144 + boff;
            uint32_t bl_ = sb + PJ_WL + (uint32_t)(8*j)*144 + boff;
            ldsm4(kb[0], kb[1], kb[2], kb[3], bh_);
            ldsm4(kb[4], kb[5], kb[6], kb[7], bh_ + 64);
            ldsm4(kbl[0], kbl[1], kbl[2], kbl[3], bl_);
            ldsm4(kbl[4], kbl[5], kbl[6], kbl[7], bl_ + 64);
            #pragma unroll
            for (int ks = 0; ks < 4; ks++) {
                mma16816(c[j], ah[ks], kb[2*ks],  kb[2*ks+1]);
                mma16816(c[j], ah[ks], kbl[2*ks], kbl[2*ks+1]);
                mma16816(c[j], al[ks], kb[2*ks],  kb[2*ks+1]);
            }
        }
        __syncthreads();
    }

    unsigned short* oh = (z==0) ? g_qh : (z==1) ? g_kh : g_vh;
    unsigned short* ol = (z==0) ? g_ql : (z==1) ? g_kl : g_vl;
    const int r0 = m0 + 16*w + g, r1 = r0 + 8;
    const int b0_ = r0 >> 12, l0_ = r0 & 4095;
    const int b1_ = r1 >> 12, l1_ = r1 & 4095;
    #pragma unroll
    for (int j = 0; j < 8; j++) {
        int col = 8*j + 2*cc;
        float bia0 = g_wb[z*512 + n0 + col], bia1 = g_wb[z*512 + n0 + col + 1];
        float v0a = c[j][0] + bia0, v1a = c[j][1] + bia1;
        float v0b = c[j][2] + bia0, v1b = c[j][3] + bia1;
        uint32_t hp, lp;
        if (z == 2) packsplit_f16(v0a, v1a, hp, lp);
        else        packsplit(v0a, v1a, hp, lp);
        size_t i0 = ((size_t)(b0_*H + head)*L + l0_)*64 + col;
        *(uint32_t*)(oh + i0) = hp; *(uint32_t*)(ol + i0) = lp;
        if (z == 2) packsplit_f16(v0b, v1b, hp, lp);
        else        packsplit(v0b, v1b, hp, lp);
        size_t i1 = ((size_t)(b1_*H + head)*L + l1_)*64 + col;
        *(uint32_t*)(oh + i1) = hp; *(uint32_t*)(ol + i1) = lp;
    }
}

// ---- attention (R11 base): S bf16x3, PV fp16; P stored fp16 to scratch -----
#define AT_BUF 36864   /* 4 arrays x 64 rows x 144B per buffer */

__global__ void __launch_bounds__(256) attn_mma(const int* __restrict__ mask) {
    extern __shared__ char smem[];
    const uint32_t sb = su32(smem);
    const int tid = threadIdx.x;
    const int w = tid >> 5, l = tid & 31;
    const int g = l >> 2, cc = l & 3;
    const int qt = blockIdx.x, h = blockIdx.y, b = blockIdx.z;
    const int bh = b*H + h;
    const int q0 = qt * 128;
    const int r0 = q0 + 16*w + g, r1 = r0 + 8;

    uint32_t qh[4][4], ql[4][4];
    #pragma unroll
    for (int ks = 0; ks < 4; ks++) {
        int cA = 16*ks + 2*cc;
        size_t i00 = ((size_t)bh*L + r0)*64 + cA;
        size_t i10 = ((size_t)bh*L + r1)*64 + cA;
        qh[ks][0] = *(const uint32_t*)(g_qh + i00);
        qh[ks][1] = *(const uint32_t*)(g_qh + i10);
        qh[ks][2] = *(const uint32_t*)(g_qh + i00 + 8);
        qh[ks][3] = *(const uint32_t*)(g_qh + i10 + 8);
        ql[ks][0] = *(const uint32_t*)(g_ql + i00);
        ql[ks][1] = *(const uint32_t*)(g_ql + i10);
        ql[ks][2] = *(const uint32_t*)(g_ql + i00 + 8);
        ql[ks][3] = *(const uint32_t*)(g_ql + i10 + 8);
    }
    const bool ok0 = g_allones[(size_t)b*L + r0] != 0;
    const bool ok1 = g_allones[(size_t)b*L + r1] != 0;
    const int* mrow0 = mask + ((size_t)b*L + r0) * (size_t)L;
    const int* mrow1 = mask + ((size_t)b*L + r1) * (size_t)L;

    const int sarr = tid >> 6;          // 0 kh, 1 kl, 2 vh, 3 vl
    const int srow = tid & 63;
    const unsigned short* sbase = (sarr==0) ? g_kh : (sarr==1) ? g_kl : (sarr==2) ? g_vh : g_vl;
    const unsigned short* ssrc = sbase + ((size_t)bh*L + srow)*64;
    const uint32_t sdst = sb + sarr*9216 + srow*144;

    const uint32_t koff = (uint32_t)(l & 7) * 144 + (uint32_t)(l >> 3) * 16;
    const uint32_t voff = (uint32_t)((l & 7) + 8*(l >> 3)) * 144;

    unsigned short* p0 = g_p + ((size_t)bh*L + r0) * (size_t)L;
    unsigned short* p1 = g_p + ((size_t)bh*L + r1) * (size_t)L;

    float oacc[8][4] = {};
    float rs0 = 0.f, rs1 = 0.f;

    #pragma unroll
    for (int sgi = 0; sgi < 8; sgi++) cpa16(sdst + sgi*16, ssrc + sgi*8);
    CPCOMMIT();

    for (int it = 0; it < 64; it++) {
        const int kc = it * 64;
        CPWAIT0();
        __syncthreads();
        if (it + 1 < 64) {
            const int nb_ = (it + 1) & 1;
            const unsigned short* s2 = ssrc + (size_t)(kc + 64)*64;
            #pragma unroll
            for (int sgi = 0; sgi < 8; sgi++) cpa16(sdst + nb_*AT_BUF + sgi*16, s2 + sgi*8);
            CPCOMMIT();
        }
        const uint32_t bufb = sb + (it & 1)*AT_BUF;
        const uint32_t khb = bufb, klb = bufb + 9216, vhb = bufb + 18432, vlb = bufb + 27648;

        uint32_t ph[4][4];
        #pragma unroll
        for (int j = 0; j < 8; j++) {
            uint32_t kb[8], kbl[8];
            uint32_t ah = khb + (uint32_t)(8*j)*144 + koff;
            uint32_t al = klb + (uint32_t)(8*j)*144 + koff;
            ldsm4(kb[0], kb[1], kb[2], kb[3], ah);
            ldsm4(kb[4], kb[5], kb[6], kb[7], ah + 64);
            ldsm4(kbl[0], kbl[1], kbl[2], kbl[3], al);
            ldsm4(kbl[4], kbl[5], kbl[6], kbl[7], al + 64);
            float sacc[4] = {0.f, 0.f, 0.f, 0.f};
            #pragma unroll
            for (int ks = 0; ks < 4; ks++) {
                mma16816(sacc, qh[ks], kb[2*ks],  kb[2*ks+1]);
                mma16816(sacc, qh[ks], kbl[2*ks], kbl[2*ks+1]);
                mma16816(sacc, ql[ks], kb[2*ks],  kb[2*ks+1]);
            }
            float e0 = ex2(sacc[0]), e1 = ex2(sacc[1]);
            float e2 = ex2(sacc[2]), e3 = ex2(sacc[3]);
            int col = kc + 8*j + 2*cc;
            if (!ok0) {
                if (!mrow0[col])   e0 = 0.f;
                if (!mrow0[col+1]) e1 = 0.f;
            }
            if (!ok1) {
                if (!mrow1[col])   e2 = 0.f;
                if (!mrow1[col+1]) e3 = 0.f;
            }
            rs0 += e0 + e1; rs1 += e2 + e3;
            int t = j >> 1, o = (j & 1) * 2;
            uint32_t pk0 = packf16(e0, e1);
            uint32_t pk1 = packf16(e2, e3);
            ph[t][o]   = pk0;
            ph[t][o+1] = pk1;
            *(uint32_t*)(p0 + col) = pk0;       // unnormalized fp16 P
            *(uint32_t*)(p1 + col) = pk1;
        }
        #pragma unroll
        for (int jd = 0; jd < 8; jd++) {
            uint32_t vb[8], vbl[8];
            #pragma unroll
            for (int tp = 0; tp < 2; tp++) {
                uint32_t ahv = vhb + (uint32_t)(32*tp)*144 + voff + (uint32_t)jd*16;
                uint32_t alv = vlb + (uint32_t)(32*tp)*144 + voff + (uint32_t)jd*16;
                ldsm4t(vb[4*tp+0],  vb[4*tp+1],  vb[4*tp+2],  vb[4*tp+3],  ahv);
                ldsm4t(vbl[4*tp+0], vbl[4*tp+1], vbl[4*tp+2], vbl[4*tp+3], alv);
            }
            #pragma unroll
            for (int t = 0; t < 4; t++) {
                mma16816f(oacc[jd], ph[t], vb[2*t],  vb[2*t+1]);
                mma16816f(oacc[jd], ph[t], vbl[2*t], vbl[2*t+1]);
            }
        }
    }

    rs0 += __shfl_xor_sync(0xffffffffu, rs0, 1);
    rs0 += __shfl_xor_sync(0xffffffffu, rs0, 2);
    rs1 += __shfl_xor_sync(0xffffffffu, rs1, 1);
    rs1 += __shfl_xor_sync(0xffffffffu, rs1, 2);
    if (cc == 0) {
        g_rowsum[(size_t)bh*L + r0] = rs0;
        g_rowsum[(size_t)bh*L + r1] = rs1;
    }
    const float rinv0 = 1.f / rs0, rinv1 = 1.f / rs1;

    #pragma unroll
    for (int jd = 0; jd < 8; jd++) {
        int col = 8*jd + 2*cc;
        uint32_t hp, lp;
        packsplit(oacc[jd][0]*rinv0, oacc[jd][1]*rinv0, hp, lp);
        size_t i0 = ((size_t)bh*L + r0)*64 + col;
        *(uint32_t*)(g_aoh + i0) = hp; *(uint32_t*)(g_aol + i0) = lp;
        packsplit(oacc[jd][2]*rinv1, oacc[jd][3]*rinv1, hp, lp);
        size_t i1 = ((size_t)bh*L + r1)*64 + col;
        *(uint32_t*)(g_aoh + i1) = hp; *(uint32_t*)(g_aol + i1) = lp;
    }
}

// ---------- normalize: read fp16 P, scale, write fp32 wout (no smem) --------
__global__ void normalize_w(float* __restrict__ wout) {
    const int row = blockIdx.x;                    // NB*H*L rows
    const float rinv = 1.f / g_rowsum[row];
    const uint2* src = (const uint2*)(g_p + (size_t)row * L);
    float4* dst = (float4*)(wout + (size_t)row * L);
    #pragma unroll
    for (int i = 0; i < 4; i++) {
        int idx = i*256 + threadIdx.x;
        uint2 pv = src[idx];
        float f0, f1, f2, f3;
        unpackf16(pv.x, f0, f1);
        unpackf16(pv.y, f2, f3);
        dst[idx] = make_float4(f0*rinv, f1*rinv, f2*rinv, f3*rinv);
    }
}

// ---------------- output projection via mma.sync bf16x3 --------------------
#define OP_AH 0
#define OP_AL 18432
#define OP_BH 36864
#define OP_BL 46080
#define OP_SZ 55296

__global__ void __launch_bounds__(256) outproj_mma(float* __restrict__ out) {
    extern __shared__ char smem[];
    const uint32_t sb = su32(smem);
    const int tid = threadIdx.x;
    const int w = tid >> 5, l = tid & 31;
    const int g = l >> 2, cc = l & 3;
    const int m0 = blockIdx.x * 128;
    const int n0 = blockIdx.y * 64;

    const int aarr = tid >> 7, arow = tid & 127;
    const int am = m0 + arow, ab = am >> 12, al_ = am & 4095;
    const unsigned short* asrc0 = (aarr ? g_aol : g_aoh);
    const uint32_t adst = sb + (aarr ? OP_AL : OP_AH) + arow*144;
    const int barr = tid >> 7, brow = (tid >> 1) & 63, bseg0 = (tid & 1) * 4;
    const unsigned short* bsrc = (barr ? g_wl : g_wh) + (size_t)3*262144 + (size_t)(n0 + brow)*512;
    const uint32_t bdst = sb + (barr ? OP_BL : OP_BH) + brow*144;

    float c[8][4] = {};
    for (int kt = 0; kt < 8; kt++) {
        const unsigned short* as = asrc0 + ((size_t)(ab*H + kt)*L + al_)*64;
        #pragma unroll
        for (int sgi = 0; sgi < 8; sgi++) cpa16(adst + sgi*16, as + sgi*8);
        #pragma unroll
        for (int i = 0; i < 4; i++) {
            int seg = bseg0 + i;
            cpa16(bdst + seg*16, bsrc + kt*64 + seg*8);
        }
        CPCOMMIT();
        CPWAIT0();
        __syncthreads();

        uint32_t ah[4][4], alr[4][4];
        const uint32_t aoff = (uint32_t)((l & 15) + 16*w) * 144 + (uint32_t)(l >> 4) * 16;
        #pragma unroll
        for (int ks = 0; ks < 4; ks++) {
            ldsm4(ah[ks][0],  ah[ks][1],  ah[ks][2],  ah[ks][3],  sb + OP_AH + aoff + ks*32);
            ldsm4(alr[ks][0], alr[ks][1], alr[ks][2], alr[ks][3], sb + OP_AL + aoff + ks*32);
        }
        const uint32_t boff = (uint32_t)(l & 7) * 144 + (uint32_t)(l >> 3) * 16;
        #pragma unroll
        for (int j = 0; j < 8; j++) {
            uint32_t kb[8], kbl[8];
            uint32_t bh_ = sb + OP_BH + (uint32_t)(8*j)*144 + boff;
            uint32_t bl_ = sb + OP_BL + (uint32_t)(8*j)*144 + boff;
            ldsm4(kb[0], kb[1], kb[2], kb[3], bh_);
            ldsm4(kb[4], kb[5], kb[6], kb[7], bh_ + 64);
            ldsm4(kbl[0], kbl[1], kbl[2], kbl[3], bl_);
            ldsm4(kbl[4], kbl[5], kbl[6], kbl[7], bl_ + 64);
            #pragma unroll
            for (int ks = 0; ks < 4; ks++) {
                mma16816(c[j], ah[ks],  kb[2*ks],  kb[2*ks+1]);
                mma16816(c[j], ah[ks],  kbl[2*ks], kbl[2*ks+1]);
                mma16816(c[j], alr[ks], kb[2*ks],  kb[2*ks+1]);
            }
        }
        __syncthreads();
    }

    const int r0 = m0 + 16*w + g, r1 = r0 + 8;
    #pragma unroll
    for (int j = 0; j < 8; j++) {
        int col = 8*j + 2*cc;
        float bia0 = g_wb[3*512 + n0 + col], bia1 = g_wb[3*512 + n0 + col + 1];
        *(float2*)(out + (size_t)r0*512 + n0 + col) = make_float2(c[j][0] + bia0, c[j][1] + bia1);
        *(float2*)(out + (size_t)r1*512 + n0 + col) = make_float2(c[j][2] + bia0, c[j][3] + bia1);
    }
}

extern "C" void kernel_launch(void* const* d_in, const int* in_sizes, int n_in,
                              void* d_out, int out_size) {
    const float* q    = (const float*)d_in[0];
    const float* k    = (const float*)d_in[1];
    const float* v    = (const float*)d_in[2];
    const int*   mask = (const int*)d_in[3];
    const float* Wq   = (const float*)d_in[4];
    const float* bq   = (const float*)d_in[5];
    const float* Wk   = (const float*)d_in[6];
    const float* bk   = (const float*)d_in[7];
    const float* Wv   = (const float*)d_in[8];
    const float* bv   = (const float*)d_in[9];
    const float* Wo   = (const float*)d_in[10];
    const float* bo   = (const float*)d_in[11];

    float* out  = (float*)d_out;                    // (N, L, 512)
    float* wout = out + (size_t)NB*L*D;             // (N, H, L, L)

    cudaFuncSetAttribute(proj_mma,    cudaFuncAttributeMaxDynamicSharedMemorySize, PJ_SZ);
    cudaFuncSetAttribute(attn_mma,    cudaFuncAttributeMaxDynamicSharedMemorySize, 2*AT_BUF);
    cudaFuncSetAttribute(outproj_mma, cudaFuncAttributeMaxDynamicSharedMemorySize, OP_SZ);

    mask_scan  <<<NB*L, 256>>>(mask);
    prep_w     <<<4096, 256>>>(Wq, Wk, Wv, Wo, bq, bk, bv, bo);
    proj_mma   <<<dim3(64,8,3), 256, PJ_SZ>>>(q, k, v);
    attn_mma   <<<dim3(32,8,2), 256, 2*AT_BUF>>>(mask);
    normalize_w<<<NB*H*L, 256>>>(wout);
    outproj_mma<<<dim3(64,8),   256, OP_SZ>>>(out);
}

// round 16
// speedup vs baseline: 1.7224x; 1.1200x over previous
#include <cuda_runtime.h>
#include <cuda_bf16.h>
#include <cstdint>

#define NB 2
#define L  4096
#define D  512
#define H  8
#define DH 64

#define SCALE 0.18033688011111793f  /* log2(e)/8 */

__device__ unsigned short g_qh[NB*H*L*DH];                    // fp16 single Q
__device__ unsigned short g_kh[NB*H*L*DH], g_kl[NB*H*L*DH];   // fp16 hi/lo K
__device__ unsigned short g_vh[NB*H*L*DH], g_vl[NB*H*L*DH];   // fp16 hi/lo V
__device__ unsigned short g_aoh[NB*H*L*DH], g_aol[NB*H*L*DH];
__device__ unsigned short g_wh[4*D*D], g_wl[4*D*D];
__device__ float g_wb[4*D];
__device__ float g_rowsum[NB*H*L];
__device__ int   g_allones[NB*L];
__device__ unsigned short g_p[(size_t)NB*H*L*L];   // fp16 unnormalized P

// ------------------------------ helpers ------------------------------------
__device__ __forceinline__ uint32_t su32(const void* p) {
    uint32_t a;
    asm("{ .reg .u64 t; cvta.to.shared.u64 t, %1; cvt.u32.u64 %0, t; }" : "=r"(a) : "l"(p));
    return a;
}
__device__ __forceinline__ float ex2(float x) {
    float r; asm("ex2.approx.f32 %0, %1;" : "=f"(r) : "f"(x)); return r;
}
__device__ __forceinline__ void packsplit(float f0, float f1, uint32_t& hp, uint32_t& lp) {
    asm("cvt.rn.bf16x2.f32 %0, %1, %2;" : "=r"(hp) : "f"(f1), "f"(f0));
    float r0 = __uint_as_float(hp << 16);
    float r1 = __uint_as_float(hp & 0xffff0000u);
    float l0 = f0 - r0, l1 = f1 - r1;
    asm("cvt.rn.bf16x2.f32 %0, %1, %2;" : "=r"(lp) : "f"(l1), "f"(l0));
}
__device__ __forceinline__ uint32_t packf16(float f0, float f1) {
    uint32_t r;
    asm("cvt.rn.f16x2.f32 %0, %1, %2;" : "=r"(r) : "f"(f1), "f"(f0));
    return r;
}
__device__ __forceinline__ void packsplit_f16(float f0, float f1, uint32_t& hp, uint32_t& lp) {
    asm("cvt.rn.f16x2.f32 %0, %1, %2;" : "=r"(hp) : "f"(f1), "f"(f0));
    float r0, r1;
    asm("{ .reg .b16 lo, hi; mov.b32 {lo, hi}, %2; cvt.f32.f16 %0, lo; cvt.f32.f16 %1, hi; }"
        : "=f"(r0), "=f"(r1) : "r"(hp));
    asm("cvt.rn.f16x2.f32 %0, %1, %2;" : "=r"(lp) : "f"(f1 - r1), "f"(f0 - r0));
}
__device__ __forceinline__ void unpackf16(uint32_t p, float& f0, float& f1) {
    asm("{ .reg .b16 a,b; mov.b32 {a,b}, %2; cvt.f32.f16 %0, a; cvt.f32.f16 %1, b; }"
        : "=f"(f0), "=f"(f1) : "r"(p));
}
__device__ __forceinline__ void ldsm4(uint32_t& r0, uint32_t& r1, uint32_t& r2, uint32_t& r3, uint32_t a) {
    asm volatile("ldmatrix.sync.aligned.m8n8.x4.shared.b16 {%0,%1,%2,%3}, [%4];"
        : "=r"(r0), "=r"(r1), "=r"(r2), "=r"(r3) : "r"(a));
}
__device__ __forceinline__ void ldsm4t(uint32_t& r0, uint32_t& r1, uint32_t& r2, uint32_t& r3, uint32_t a) {
    asm volatile("ldmatrix.sync.aligned.m8n8.x4.trans.shared.b16 {%0,%1,%2,%3}, [%4];"
        : "=r"(r0), "=r"(r1), "=r"(r2), "=r"(r3) : "r"(a));
}
__device__ __forceinline__ void mma16816(float c[4], const uint32_t a[4], uint32_t b0, uint32_t b1) {
    asm volatile("mma.sync.aligned.m16n8k16.row.col.f32.bf16.bf16.f32 "
        "{%0,%1,%2,%3},{%4,%5,%6,%7},{%8,%9},{%0,%1,%2,%3};"
        : "+f"(c[0]), "+f"(c[1]), "+f"(c[2]), "+f"(c[3])
        : "r"(a[0]), "r"(a[1]), "r"(a[2]), "r"(a[3]), "r"(b0), "r"(b1));
}
__device__ __forceinline__ void mma16816f(float c[4], const uint32_t a[4], uint32_t b0, uint32_t b1) {
    asm volatile("mma.sync.aligned.m16n8k16.row.col.f32.f16.f16.f32 "
        "{%0,%1,%2,%3},{%4,%5,%6,%7},{%8,%9},{%0,%1,%2,%3};"
        : "+f"(c[0]), "+f"(c[1]), "+f"(c[2]), "+f"(c[3])
        : "r"(a[0]), "r"(a[1]), "r"(a[2]), "r"(a[3]), "r"(b0), "r"(b1));
}
__device__ __forceinline__ void cpa16(uint32_t dst, const void* src) {
    asm volatile("cp.async.cg.shared.global [%0], [%1], 16;"
        :: "r"(dst), "l"(__cvta_generic_to_global(src)));
}
#define CPCOMMIT() asm volatile("cp.async.commit_group;" ::: "memory")
#define CPWAIT0()  asm volatile("cp.async.wait_group 0;" ::: "memory")

// ------------------------------ mask pre-scan ------------------------------
__global__ void mask_scan(const int* __restrict__ mask) {
    int row = blockIdx.x;
    const int4* m = (const int4*)(mask + (size_t)row * L);
    int ok = 1;
    for (int i = threadIdx.x; i < L/4; i += 256) {
        int4 v = m[i];
        ok &= (v.x != 0) & (v.y != 0) & (v.z != 0) & (v.w != 0);
    }
    ok = __syncthreads_and(ok);
    if (threadIdx.x == 0) g_allones[row] = ok;
}

// --------------------- weight prep: bf16 hi/lo split ------------------------
__global__ void prep_w(const float* __restrict__ Wq, const float* __restrict__ Wk,
                       const float* __restrict__ Wv, const float* __restrict__ Wo,
                       const float* __restrict__ bq, const float* __restrict__ bk,
                       const float* __restrict__ bv, const float* __restrict__ bo) {
    int idx = blockIdx.x * 256 + threadIdx.x;
    int mat = idx >> 18;
    int rem = idx & 262143;
    const float* W = (mat==0) ? Wq : (mat==1) ? Wk : (mat==2) ? Wv : Wo;
    float v = W[rem];
    if (mat == 0) v *= SCALE;
    __nv_bfloat16 hb = __float2bfloat16(v);
    float r = __bfloat162float(hb);
    __nv_bfloat16 lb = __float2bfloat16(v - r);
    g_wh[idx] = *(unsigned short*)&hb;
    g_wl[idx] = *(unsigned short*)&lb;
    if (idx < 4*D) {
        int m2 = idx >> 9, n = idx & 511;
        const float* B = (m2==0) ? bq : (m2==1) ? bk : (m2==2) ? bv : bo;
        float bvl = B[n];
        if (m2 == 0) bvl *= SCALE;
        g_wb[idx] = bvl;
    }
}

// ---------------- QKV projections via mma.sync bf16x3 -----------------------
// Q out: single fp16. K/V out: fp16 hi/lo.
#define PJ_XH 0
#define PJ_XL 18432
#define PJ_WH 36864
#define PJ_WL 46080
#define PJ_SZ 55296

__global__ void __launch_bounds__(256) proj_mma(const float* __restrict__ xq,
                                                const float* __restrict__ xk,
                                                const float* __restrict__ xv) {
    extern __shared__ char smem[];
    const uint32_t sb = su32(smem);
    const int tid = threadIdx.x;
    const int w = tid >> 5, l = tid & 31;
    const int g = l >> 2, cc = l & 3;
    const int m0 = blockIdx.x * 128;
    const int head = blockIdx.y;
    const int z = blockIdx.z;
    const int n0 = head * 64;
    const float* X = (z==0) ? xq : (z==1) ? xk : xv;

    const int warr = tid >> 7;
    const int wrow = (tid >> 1) & 63;
    const int wseg0 = (tid & 1) * 4;
    const unsigned short* wsrc = (warr ? g_wl : g_wh) + (size_t)z*262144 + (size_t)(n0 + wrow)*512;
    const uint32_t wdst = sb + (warr ? PJ_WL : PJ_WH) + wrow*144;

    const int xrow = tid >> 1, xhalf = tid & 1;

    float c[8][4] = {};
    for (int kt = 0; kt < 8; kt++) {
        #pragma unroll
        for (int i = 0; i < 4; i++) {
            int seg = wseg0 + i;
            cpa16(wdst + seg*16, wsrc + kt*64 + seg*8);
        }
        CPCOMMIT();
        #pragma unroll
        for (int jj = 0; jj < 8; jj++) {
            int col = xhalf*32 + jj*4;
            float4 v = *(const float4*)(X + (size_t)(m0 + xrow)*512 + kt*64 + col);
            uint32_t h0,l0,h1,l1;
            packsplit(v.x, v.y, h0, l0); packsplit(v.z, v.w, h1, l1);
            *(uint2*)(smem + PJ_XH + xrow*144 + col*2) = make_uint2(h0, h1);
            *(uint2*)(smem + PJ_XL + xrow*144 + col*2) = make_uint2(l0, l1);
        }
        CPWAIT0();
        __syncthreads();

        uint32_t ah[4][4], al[4][4];
        const uint32_t aoff = (uint32_t)((l & 15) + 16*w) * 144 + (uint32_t)(l >> 4) * 16;
        #pragma unroll
        for (int ks = 0; ks < 4; ks++) {
            ldsm4(ah[ks][0], ah[ks][1], ah[ks][2], ah[ks][3], sb + PJ_XH + aoff + ks*32);
            ldsm4(al[ks][0], al[ks][1], al[ks][2], al[ks][3], sb + PJ_XL + aoff + ks*32);
        }
        const uint32_t boff = (uint32_t)(l & 7) * 144 + (uint32_t)(l >> 3) * 16;
        #pragma unroll
        for (int j = 0; j < 8; j++) {
            uint32_t kb[8], kbl[8];
            uint32_t bh_ = sb + PJ_WH + (uint32_t)(8*j)*144 + boff;
            uint32_t bl_ = sb + PJ_WL + (uint32_t)(8*j)*144 + boff;
            ldsm4(kb[0], kb[1], kb[2], kb[3], bh_);
            ldsm4(kb[4], kb[5], kb[6], kb[7], bh_ + 64);
            ldsm4(kbl[0], kbl[1], kbl[2], kbl[3], bl_);
            ldsm4(kbl[4], kbl[5], kbl[6], kbl[7], bl_ + 64);
            #pragma unroll
            for (int ks = 0; ks < 4; ks++) {
                mma16816(c[j], ah[ks], kb[2*ks],  kb[2*ks+1]);
                mma16816(c[j], ah[ks], kbl[2*ks], kbl[2*ks+1]);
                mma16816(c[j], al[ks], kb[2*ks],  kb[2*ks+1]);
            }
        }
        __syncthreads();
    }

    const int r0 = m0 + 16*w + g, r1 = r0 + 8;
    const int b0_ = r0 >> 12, l0_ = r0 & 4095;
    const int b1_ = r1 >> 12, l1_ = r1 & 4095;
    #pragma unroll
    for (int j = 0; j < 8; j++) {
        int col = 8*j + 2*cc;
        float bia0 = g_wb[z*512 + n0 + col], bia1 = g_wb[z*512 + n0 + col + 1];
        float v0a = c[j][0] + bia0, v1a = c[j][1] + bia1;
        float v0b = c[j][2] + bia0, v1b = c[j][3] + bia1;
        size_t i0 = ((size_t)(b0_*H + head)*L + l0_)*64 + col;
        size_t i1 = ((size_t)(b1_*H + head)*L + l1_)*64 + col;
        if (z == 0) {
            *(uint32_t*)(g_qh + i0) = packf16(v0a, v1a);
            *(uint32_t*)(g_qh + i1) = packf16(v0b, v1b);
        } else {
            unsigned short* oh = (z==1) ? g_kh : g_vh;
            unsigned short* ol = (z==1) ? g_kl : g_vl;
            uint32_t hp, lp;
            packsplit_f16(v0a, v1a, hp, lp);
            *(uint32_t*)(oh + i0) = hp; *(uint32_t*)(ol + i0) = lp;
            packsplit_f16(v0b, v1b, hp, lp);
            *(uint32_t*)(oh + i1) = hp; *(uint32_t*)(ol + i1) = lp;
        }
    }
}

// ---- attention: S fp16x2 (q single, K hi/lo), PV fp16; fp16 P scratch ------
#define AT_BUF 36864   /* 4 arrays x 64 rows x 144B per buffer */

__global__ void __launch_bounds__(256) attn_mma(const int* __restrict__ mask) {
    extern __shared__ char smem[];
    const uint32_t sb = su32(smem);
    const int tid = threadIdx.x;
    const int w = tid >> 5, l = tid & 31;
    const int g = l >> 2, cc = l & 3;
    const int qt = blockIdx.x, h = blockIdx.y, b = blockIdx.z;
    const int bh = b*H + h;
    const int q0 = qt * 128;
    const int r0 = q0 + 16*w + g, r1 = r0 + 8;

    uint32_t qh[4][4];
    #pragma unroll
    for (int ks = 0; ks < 4; ks++) {
        int cA = 16*ks + 2*cc;
        size_t i00 = ((size_t)bh*L + r0)*64 + cA;
        size_t i10 = ((size_t)bh*L + r1)*64 + cA;
        qh[ks][0] = *(const uint32_t*)(g_qh + i00);
        qh[ks][1] = *(const uint32_t*)(g_qh + i10);
        qh[ks][2] = *(const uint32_t*)(g_qh + i00 + 8);
        qh[ks][3] = *(const uint32_t*)(g_qh + i10 + 8);
    }
    const bool ok0 = g_allones[(size_t)b*L + r0] != 0;
    const bool ok1 = g_allones[(size_t)b*L + r1] != 0;
    const int* mrow0 = mask + ((size_t)b*L + r0) * (size_t)L;
    const int* mrow1 = mask + ((size_t)b*L + r1) * (size_t)L;

    const int sarr = tid >> 6;          // 0 kh, 1 kl, 2 vh, 3 vl
    const int srow = tid & 63;
    const unsigned short* sbase = (sarr==0) ? g_kh : (sarr==1) ? g_kl : (sarr==2) ? g_vh : g_vl;
    const unsigned short* ssrc = sbase + ((size_t)bh*L + srow)*64;
    const uint32_t sdst = sb + sarr*9216 + srow*144;

    const uint32_t koff = (uint32_t)(l & 7) * 144 + (uint32_t)(l >> 3) * 16;
    const uint32_t voff = (uint32_t)((l & 7) + 8*(l >> 3)) * 144;

    unsigned short* p0 = g_p + ((size_t)bh*L + r0) * (size_t)L;
    unsigned short* p1 = g_p + ((size_t)bh*L + r1) * (size_t)L;

    float oacc[8][4] = {};
    float rs0 = 0.f, rs1 = 0.f;

    #pragma unroll
    for (int sgi = 0; sgi < 8; sgi++) cpa16(sdst + sgi*16, ssrc + sgi*8);
    CPCOMMIT();

    for (int it = 0; it < 64; it++) {
        const int kc = it * 64;
        CPWAIT0();
        __syncthreads();
        if (it + 1 < 64) {
            const int nb_ = (it + 1) & 1;
            const unsigned short* s2 = ssrc + (size_t)(kc + 64)*64;
            #pragma unroll
            for (int sgi = 0; sgi < 8; sgi++) cpa16(sdst + nb_*AT_BUF + sgi*16, s2 + sgi*8);
            CPCOMMIT();
        }
        const uint32_t bufb = sb + (it & 1)*AT_BUF;
        const uint32_t khb = bufb, klb = bufb + 9216, vhb = bufb + 18432, vlb = bufb + 27648;

        uint32_t ph[4][4];
        #pragma unroll
        for (int j = 0; j < 8; j++) {
            uint32_t kb[8], kbl[8];
            uint32_t ah = khb + (uint32_t)(8*j)*144 + koff;
            uint32_t al = klb + (uint32_t)(8*j)*144 + koff;
            ldsm4(kb[0], kb[1], kb[2], kb[3], ah);
            ldsm4(kb[4], kb[5], kb[6], kb[7], ah + 64);
            ldsm4(kbl[0], kbl[1], kbl[2], kbl[3], al);
            ldsm4(kbl[4], kbl[5], kbl[6], kbl[7], al + 64);
            float sacc[4] = {0.f, 0.f, 0.f, 0.f};
            #pragma unroll
            for (int ks = 0; ks < 4; ks++) {
                mma16816f(sacc, qh[ks], kb[2*ks],  kb[2*ks+1]);
                mma16816f(sacc, qh[ks], kbl[2*ks], kbl[2*ks+1]);
            }
            float e0 = ex2(sacc[0]), e1 = ex2(sacc[1]);
            float e2 = ex2(sacc[2]), e3 = ex2(sacc[3]);
            int col = kc + 8*j + 2*cc;
            if (!ok0) {
                if (!mrow0[col])   e0 = 0.f;
                if (!mrow0[col+1]) e1 = 0.f;
            }
            if (!ok1) {
                if (!mrow1[col])   e2 = 0.f;
                if (!mrow1[col+1]) e3 = 0.f;
            }
            rs0 += e0 + e1; rs1 += e2 + e3;
            int t = j >> 1, o = (j & 1) * 2;
            uint32_t pk0 = packf16(e0, e1);
            uint32_t pk1 = packf16(e2, e3);
            ph[t][o]   = pk0;
            ph[t][o+1] = pk1;
            *(uint32_t*)(p0 + col) = pk0;
            *(uint32_t*)(p1 + col) = pk1;
        }
        #pragma unroll
        for (int jd = 0; jd < 8; jd++) {
            uint32_t vb[8], vbl[8];
            #pragma unroll
            for (int tp = 0; tp < 2; tp++) {
                uint32_t ahv = vhb + (uint32_t)(32*tp)*144 + voff + (uint32_t)jd*16;
                uint32_t alv = vlb + (uint32_t)(32*tp)*144 + voff + (uint32_t)jd*16;
                ldsm4t(vb[4*tp+0],  vb[4*tp+1],  vb[4*tp+2],  vb[4*tp+3],  ahv);
                ldsm4t(vbl[4*tp+0], vbl[4*tp+1], vbl[4*tp+2], vbl[4*tp+3], alv);
            }
            #pragma unroll
            for (int t = 0; t < 4; t++) {
                mma16816f(oacc[jd], ph[t], vb[2*t],  vb[2*t+1]);
                mma16816f(oacc[jd], ph[t], vbl[2*t], vbl[2*t+1]);
            }
        }
    }

    rs0 += __shfl_xor_sync(0xffffffffu, rs0, 1);
    rs0 += __shfl_xor_sync(0xffffffffu, rs0, 2);
    rs1 += __shfl_xor_sync(0xffffffffu, rs1, 1);
    rs1 += __shfl_xor_sync(0xffffffffu, rs1, 2);
    if (cc == 0) {
        g_rowsum[(size_t)bh*L + r0] = rs0;
        g_rowsum[(size_t)bh*L + r1] = rs1;
    }
    const float rinv0 = 1.f / rs0, rinv1 = 1.f / rs1;

    #pragma unroll
    for (int jd = 0; jd < 8; jd++) {
        int col = 8*jd + 2*cc;
        uint32_t hp, lp;
        packsplit(oacc[jd][0]*rinv0, oacc[jd][1]*rinv0, hp, lp);
        size_t i0 = ((size_t)bh*L + r0)*64 + col;
        *(uint32_t*)(g_aoh + i0) = hp; *(uint32_t*)(g_aol + i0) = lp;
        packsplit(oacc[jd][2]*rinv1, oacc[jd][3]*rinv1, hp, lp);
        size_t i1 = ((size_t)bh*L + r1)*64 + col;
        *(uint32_t*)(g_aoh + i1) = hp; *(uint32_t*)(g_aol + i1) = lp;
    }
}

// ---------- normalize: read fp16 P, scale, write fp32 wout (no smem) --------
__global__ void normalize_w(float* __restrict__ wout) {
    const int row = blockIdx.x;
    const float rinv = 1.f / g_rowsum[row];
    const uint2* src = (const uint2*)(g_p + (size_t)row * L);
    float4* dst = (float4*)(wout + (size_t)row * L);
    #pragma unroll
    for (int i = 0; i < 4; i++) {
        int idx = i*256 + threadIdx.x;
        uint2 pv = src[idx];
        float f0, f1, f2, f3;
        unpackf16(pv.x, f0, f1);
        unpackf16(pv.y, f2, f3);
        dst[idx] = make_float4(f0*rinv, f1*rinv, f2*rinv, f3*rinv);
    }
}

// ---------------- output projection via mma.sync bf16x3 --------------------
#define OP_AH 0
#define OP_AL 18432
#define OP_BH 36864
#define OP_BL 46080
#define OP_SZ 55296

__global__ void __launch_bounds__(256) outproj_mma(float* __restrict__ out) {
    extern __shared__ char smem[];
    const uint32_t sb = su32(smem);
    const int tid = threadIdx.x;
    const int w = tid >> 5, l = tid & 31;
    const int g = l >> 2, cc = l & 3;
    const int m0 = blockIdx.x * 128;
    const int n0 = blockIdx.y * 64;

    const int aarr = tid >> 7, arow = tid & 127;
    const int am = m0 + arow, ab = am >> 12, al_ = am & 4095;
    const unsigned short* asrc0 = (aarr ? g_aol : g_aoh);
    const uint32_t adst = sb + (aarr ? OP_AL : OP_AH) + arow*144;
    const int barr = tid >> 7, brow = (tid >> 1) & 63, bseg0 = (tid & 1) * 4;
    const unsigned short* bsrc = (barr ? g_wl : g_wh) + (size_t)3*262144 + (size_t)(n0 + brow)*512;
    const uint32_t bdst = sb + (barr ? OP_BL : OP_BH) + brow*144;

    float c[8][4] = {};
    for (int kt = 0; kt < 8; kt++) {
        const unsigned short* as = asrc0 + ((size_t)(ab*H + kt)*L + al_)*64;
        #pragma unroll
        for (int sgi = 0; sgi < 8; sgi++) cpa16(adst + sgi*16, as + sgi*8);
        #pragma unroll
        for (int i = 0; i < 4; i++) {
            int seg = bseg0 + i;
            cpa16(bdst + seg*16, bsrc + kt*64 + seg*8);
        }
        CPCOMMIT();
        CPWAIT0();
        __syncthreads();

        uint32_t ah[4][4], alr[4][4];
        const uint32_t aoff = (uint32_t)((l & 15) + 16*w) * 144 + (uint32_t)(l >> 4) * 16;
        #pragma unroll
        for (int ks = 0; ks < 4; ks++) {
            ldsm4(ah[ks][0],  ah[ks][1],  ah[ks][2],  ah[ks][3],  sb + OP_AH + aoff + ks*32);
            ldsm4(alr[ks][0], alr[ks][1], alr[ks][2], alr[ks][3], sb + OP_AL + aoff + ks*32);
        }
        const uint32_t boff = (uint32_t)(l & 7) * 144 + (uint32_t)(l >> 3) * 16;
        #pragma unroll
        for (int j = 0; j < 8; j++) {
            uint32_t kb[8], kbl[8];
            uint32_t bh_ = sb + OP_BH + (uint32_t)(8*j)*144 + boff;
            uint32_t bl_ = sb + OP_BL + (uint32_t)(8*j)*144 + boff;
            ldsm4(kb[0], kb[1], kb[2], kb[3], bh_);
            ldsm4(kb[4], kb[5], kb[6], kb[7], bh_ + 64);
            ldsm4(kbl[0], kbl[1], kbl[2], kbl[3], bl_);
            ldsm4(kbl[4], kbl[5], kbl[6], kbl[7], bl_ + 64);
            #pragma unroll
            for (int ks = 0; ks < 4; ks++) {
                mma16816(c[j], ah[ks],  kb[2*ks],  kb[2*ks+1]);
                mma16816(c[j], ah[ks],  kbl[2*ks], kbl[2*ks+1]);
                mma16816(c[j], alr[ks], kb[2*ks],  kb[2*ks+1]);
            }
        }
        __syncthreads();
    }

    const int r0 = m0 + 16*w + g, r1 = r0 + 8;
    #pragma unroll
    for (int j = 0; j < 8; j++) {
        int col = 8*j + 2*cc;
        float bia0 = g_wb[3*512 + n0 + col], bia1 = g_wb[3*512 + n0 + col + 1];
        *(float2*)(out + (size_t)r0*512 + n0 + col) = make_float2(c[j][0] + bia0, c[j][1] + bia1);
        *(float2*)(out + (size_t)r1*512 + n0 + col) = make_float2(c[j][2] + bia0, c[j][3] + bia1);
    }
}

extern "C" void kernel_launch(void* const* d_in, const int* in_sizes, int n_in,
                              void* d_out, int out_size) {
    const float* q    = (const float*)d_in[0];
    const float* k    = (const float*)d_in[1];
    const float* v    = (const float*)d_in[2];
    const int*   mask = (const int*)d_in[3];
    const float* Wq   = (const float*)d_in[4];
    const float* bq   = (const float*)d_in[5];
    const float* Wk   = (const float*)d_in[6];
    const float* bk   = (const float*)d_in[7];
    const float* Wv   = (const float*)d_in[8];
    const float* bv   = (const float*)d_in[9];
    const float* Wo   = (const float*)d_in[10];
    const float* bo   = (const float*)d_in[11];

    float* out  = (float*)d_out;                    // (N, L, 512)
    float* wout = out + (size_t)NB*L*D;             // (N, H, L, L)

    cudaFuncSetAttribute(proj_mma,    cudaFuncAttributeMaxDynamicSharedMemorySize, PJ_SZ);
    cudaFuncSetAttribute(attn_mma,    cudaFuncAttributeMaxDynamicSharedMemorySize, 2*AT_BUF);
    cudaFuncSetAttribute(outproj_mma, cudaFuncAttributeMaxDynamicSharedMemorySize, OP_SZ);

    mask_scan  <<<NB*L, 256>>>(mask);
    prep_w     <<<4096, 256>>>(Wq, Wk, Wv, Wo, bq, bk, bv, bo);
    proj_mma   <<<dim3(64,8,3), 256, PJ_SZ>>>(q, k, v);
    attn_mma   <<<dim3(32,8,2), 256, 2*AT_BUF>>>(mask);
    normalize_w<<<NB*H*L, 256>>>(wout);
    outproj_mma<<<dim3(64,8),   256, OP_SZ>>>(out);
}

// round 17
// speedup vs baseline: 2.2437x; 1.3027x over previous
#include <cuda_runtime.h>
#include <cuda_bf16.h>
#include <cstdint>

#define NB 2
#define L  4096
#define D  512
#define H  8
#define DH 64

#define SCALE 0.18033688011111793f  /* log2(e)/8 */

__device__ unsigned short g_qh[NB*H*L*DH];   // fp16 Q
__device__ unsigned short g_kh[NB*H*L*DH];   // fp16 K
__device__ unsigned short g_vh[NB*H*L*DH];   // fp16 V
__device__ unsigned short g_aoh[NB*H*L*DH], g_aol[NB*H*L*DH];
__device__ unsigned short g_wh[4*D*D], g_wl[4*D*D];
__device__ float g_wb[4*D];
__device__ float g_rowsum[NB*H*L];
__device__ int   g_allones[NB*L];
__device__ unsigned short g_p[(size_t)NB*H*L*L];   // fp16 unnormalized P

// ------------------------------ helpers ------------------------------------
__device__ __forceinline__ uint32_t su32(const void* p) {
    uint32_t a;
    asm("{ .reg .u64 t; cvta.to.shared.u64 t, %1; cvt.u32.u64 %0, t; }" : "=r"(a) : "l"(p));
    return a;
}
__device__ __forceinline__ float ex2(float x) {
    float r; asm("ex2.approx.f32 %0, %1;" : "=f"(r) : "f"(x)); return r;
}
__device__ __forceinline__ void packsplit(float f0, float f1, uint32_t& hp, uint32_t& lp) {
    asm("cvt.rn.bf16x2.f32 %0, %1, %2;" : "=r"(hp) : "f"(f1), "f"(f0));
    float r0 = __uint_as_float(hp << 16);
    float r1 = __uint_as_float(hp & 0xffff0000u);
    float l0 = f0 - r0, l1 = f1 - r1;
    asm("cvt.rn.bf16x2.f32 %0, %1, %2;" : "=r"(lp) : "f"(l1), "f"(l0));
}
__device__ __forceinline__ uint32_t packf16(float f0, float f1) {
    uint32_t r;
    asm("cvt.rn.f16x2.f32 %0, %1, %2;" : "=r"(r) : "f"(f1), "f"(f0));
    return r;
}
__device__ __forceinline__ void unpackf16(uint32_t p, float& f0, float& f1) {
    asm("{ .reg .b16 a,b; mov.b32 {a,b}, %2; cvt.f32.f16 %0, a; cvt.f32.f16 %1, b; }"
        : "=f"(f0), "=f"(f1) : "r"(p));
}
__device__ __forceinline__ void ldsm4(uint32_t& r0, uint32_t& r1, uint32_t& r2, uint32_t& r3, uint32_t a) {
    asm volatile("ldmatrix.sync.aligned.m8n8.x4.shared.b16 {%0,%1,%2,%3}, [%4];"
        : "=r"(r0), "=r"(r1), "=r"(r2), "=r"(r3) : "r"(a));
}
__device__ __forceinline__ void ldsm4t(uint32_t& r0, uint32_t& r1, uint32_t& r2, uint32_t& r3, uint32_t a) {
    asm volatile("ldmatrix.sync.aligned.m8n8.x4.trans.shared.b16 {%0,%1,%2,%3}, [%4];"
        : "=r"(r0), "=r"(r1), "=r"(r2), "=r"(r3) : "r"(a));
}
__device__ __forceinline__ void mma16816(float c[4], const uint32_t a[4], uint32_t b0, uint32_t b1) {
    asm volatile("mma.sync.aligned.m16n8k16.row.col.f32.bf16.bf16.f32 "
        "{%0,%1,%2,%3},{%4,%5,%6,%7},{%8,%9},{%0,%1,%2,%3};"
        : "+f"(c[0]), "+f"(c[1]), "+f"(c[2]), "+f"(c[3])
        : "r"(a[0]), "r"(a[1]), "r"(a[2]), "r"(a[3]), "r"(b0), "r"(b1));
}
__device__ __forceinline__ void mma16816f(float c[4], const uint32_t a[4], uint32_t b0, uint32_t b1) {
    asm volatile("mma.sync.aligned.m16n8k16.row.col.f32.f16.f16.f32 "
        "{%0,%1,%2,%3},{%4,%5,%6,%7},{%8,%9},{%0,%1,%2,%3};"
        : "+f"(c[0]), "+f"(c[1]), "+f"(c[2]), "+f"(c[3])
        : "r"(a[0]), "r"(a[1]), "r"(a[2]), "r"(a[3]), "r"(b0), "r"(b1));
}
__device__ __forceinline__ void cpa16(uint32_t dst, const void* src) {
    asm volatile("cp.async.cg.shared.global [%0], [%1], 16;"
        :: "r"(dst), "l"(__cvta_generic_to_global(src)));
}
#define CPCOMMIT() asm volatile("cp.async.commit_group;" ::: "memory")
#define CPWAIT0()  asm volatile("cp.async.wait_group 0;" ::: "memory")

// ------------------------------ mask pre-scan ------------------------------
__global__ void mask_scan(const int* __restrict__ mask) {
    int row = blockIdx.x;
    const int4* m = (const int4*)(mask + (size_t)row * L);
    int ok = 1;
    for (int i = threadIdx.x; i < L/4; i += 256) {
        int4 v = m[i];
        ok &= (v.x != 0) & (v.y != 0) & (v.z != 0) & (v.w != 0);
    }
    ok = __syncthreads_and(ok);
    if (threadIdx.x == 0) g_allones[row] = ok;
}

// --------------------- weight prep: bf16 hi/lo split ------------------------
__global__ void prep_w(const float* __restrict__ Wq, const float* __restrict__ Wk,
                       const float* __restrict__ Wv, const float* __restrict__ Wo,
                       const float* __restrict__ bq, const float* __restrict__ bk,
                       const float* __restrict__ bv, const float* __restrict__ bo) {
    int idx = blockIdx.x * 256 + threadIdx.x;
    int mat = idx >> 18;
    int rem = idx & 262143;
    const float* W = (mat==0) ? Wq : (mat==1) ? Wk : (mat==2) ? Wv : Wo;
    float v = W[rem];
    if (mat == 0) v *= SCALE;
    __nv_bfloat16 hb = __float2bfloat16(v);
    float r = __bfloat162float(hb);
    __nv_bfloat16 lb = __float2bfloat16(v - r);
    g_wh[idx] = *(unsigned short*)&hb;
    g_wl[idx] = *(unsigned short*)&lb;
    if (idx < 4*D) {
        int m2 = idx >> 9, n = idx & 511;
        const float* B = (m2==0) ? bq : (m2==1) ? bk : (m2==2) ? bv : bo;
        float bvl = B[n];
        if (m2 == 0) bvl *= SCALE;
        g_wb[idx] = bvl;
    }
}

// ---------------- QKV projections via mma.sync bf16x3 -----------------------
// Q/K/V all output single fp16.
#define PJ_XH 0
#define PJ_XL 18432
#define PJ_WH 36864
#define PJ_WL 46080
#define PJ_SZ 55296

__global__ void __launch_bounds__(256) proj_mma(const float* __restrict__ xq,
                                                const float* __restrict__ xk,
                                                const float* __restrict__ xv) {
    extern __shared__ char smem[];
    const uint32_t sb = su32(smem);
    const int tid = threadIdx.x;
    const int w = tid >> 5, l = tid & 31;
    const int g = l >> 2, cc = l & 3;
    const int m0 = blockIdx.x * 128;
    const int head = blockIdx.y;
    const int z = blockIdx.z;
    const int n0 = head * 64;
    const float* X = (z==0) ? xq : (z==1) ? xk : xv;

    const int warr = tid >> 7;
    const int wrow = (tid >> 1) & 63;
    const int wseg0 = (tid & 1) * 4;
    const unsigned short* wsrc = (warr ? g_wl : g_wh) + (size_t)z*262144 + (size_t)(n0 + wrow)*512;
    const uint32_t wdst = sb + (warr ? PJ_WL : PJ_WH) + wrow*144;

    const int xrow = tid >> 1, xhalf = tid & 1;

    float c[8][4] = {};
    for (int kt = 0; kt < 8; kt++) {
        #pragma unroll
        for (int i = 0; i < 4; i++) {
            int seg = wseg0 + i;
            cpa16(wdst + seg*16, wsrc + kt*64 + seg*8);
        }
        CPCOMMIT();
        #pragma unroll
        for (int jj = 0; jj < 8; jj++) {
            int col = xhalf*32 + jj*4;
            float4 v = *(const float4*)(X + (size_t)(m0 + xrow)*512 + kt*64 + col);
            uint32_t h0,l0,h1,l1;
            packsplit(v.x, v.y, h0, l0); packsplit(v.z, v.w, h1, l1);
            *(uint2*)(smem + PJ_XH + xrow*144 + col*2) = make_uint2(h0, h1);
            *(uint2*)(smem + PJ_XL + xrow*144 + col*2) = make_uint2(l0, l1);
        }
        CPWAIT0();
        __syncthreads();

        uint32_t ah[4][4], al[4][4];
        const uint32_t aoff = (uint32_t)((l & 15) + 16*w) * 144 + (uint32_t)(l >> 4) * 16;
        #pragma unroll
        for (int ks = 0; ks < 4; ks++) {
            ldsm4(ah[ks][0], ah[ks][1], ah[ks][2], ah[ks][3], sb + PJ_XH + aoff + ks*32);
            ldsm4(al[ks][0], al[ks][1], al[ks][2], al[ks][3], sb + PJ_XL + aoff + ks*32);
        }
        const uint32_t boff = (uint32_t)(l & 7) * 144 + (uint32_t)(l >> 3) * 16;
        #pragma unroll
        for (int j = 0; j < 8; j++) {
            uint32_t kb[8], kbl[8];
            uint32_t bh_ = sb + PJ_WH + (uint32_t)(8*j)*144 + boff;
            uint32_t bl_ = sb + PJ_WL + (uint32_t)(8*j)*144 + boff;
            ldsm4(kb[0], kb[1], kb[2], kb[3], bh_);
            ldsm4(kb[4], kb[5], kb[6], kb[7], bh_ + 64);
            ldsm4(kbl[0], kbl[1], kbl[2], kbl[3], bl_);
            ldsm4(kbl[4], kbl[5], kbl[6], kbl[7], bl_ + 64);
            #pragma unroll
            for (int ks = 0; ks < 4; ks++) {
                mma16816(c[j], ah[ks], kb[2*ks],  kb[2*ks+1]);
                mma16816(c[j], ah[ks], kbl[2*ks], kbl[2*ks+1]);
                mma16816(c[j], al[ks], kb[2*ks],  kb[2*ks+1]);
            }
        }
        __syncthreads();
    }

    unsigned short* oq = (z==0) ? g_qh : (z==1) ? g_kh : g_vh;
    const int r0 = m0 + 16*w + g, r1 = r0 + 8;
    const int b0_ = r0 >> 12, l0_ = r0 & 4095;
    const int b1_ = r1 >> 12, l1_ = r1 & 4095;
    #pragma unroll
    for (int j = 0; j < 8; j++) {
        int col = 8*j + 2*cc;
        float bia0 = g_wb[z*512 + n0 + col], bia1 = g_wb[z*512 + n0 + col + 1];
        size_t i0 = ((size_t)(b0_*H + head)*L + l0_)*64 + col;
        size_t i1 = ((size_t)(b1_*H + head)*L + l1_)*64 + col;
        *(uint32_t*)(oq + i0) = packf16(c[j][0] + bia0, c[j][1] + bia1);
        *(uint32_t*)(oq + i1) = packf16(c[j][2] + bia0, c[j][3] + bia1);
    }
}

// ---- attention: all-fp16 MMA (S: 4/j, PV: 4/jd); fp16 P scratch ------------
#define AT_BUF 18432   /* 2 arrays x 64 rows x 144B per buffer */

__global__ void __launch_bounds__(256) attn_mma(const int* __restrict__ mask) {
    extern __shared__ char smem[];
    const uint32_t sb = su32(smem);
    const int tid = threadIdx.x;
    const int w = tid >> 5, l = tid & 31;
    const int g = l >> 2, cc = l & 3;
    const int qt = blockIdx.x, h = blockIdx.y, b = blockIdx.z;
    const int bh = b*H + h;
    const int q0 = qt * 128;
    const int r0 = q0 + 16*w + g, r1 = r0 + 8;

    uint32_t qh[4][4];
    #pragma unroll
    for (int ks = 0; ks < 4; ks++) {
        int cA = 16*ks + 2*cc;
        size_t i00 = ((size_t)bh*L + r0)*64 + cA;
        size_t i10 = ((size_t)bh*L + r1)*64 + cA;
        qh[ks][0] = *(const uint32_t*)(g_qh + i00);
        qh[ks][1] = *(const uint32_t*)(g_qh + i10);
        qh[ks][2] = *(const uint32_t*)(g_qh + i00 + 8);
        qh[ks][3] = *(const uint32_t*)(g_qh + i10 + 8);
    }
    const bool ok0 = g_allones[(size_t)b*L + r0] != 0;
    const bool ok1 = g_allones[(size_t)b*L + r1] != 0;
    const int* mrow0 = mask + ((size_t)b*L + r0) * (size_t)L;
    const int* mrow1 = mask + ((size_t)b*L + r1) * (size_t)L;

    // staging: 2 arrays x 64 rows; 256 threads -> half a row (4 segs) each
    const int sarr = tid >> 7;                 // 0 k, 1 v
    const int srow = (tid >> 1) & 63;
    const int sg0  = (tid & 1) * 4;
    const unsigned short* sbase = sarr ? g_vh : g_kh;
    const unsigned short* ssrc = sbase + ((size_t)bh*L + srow)*64 + sg0*8;
    const uint32_t sdst = sb + sarr*9216 + srow*144 + sg0*16;

    const uint32_t koff = (uint32_t)(l & 7) * 144 + (uint32_t)(l >> 3) * 16;
    const uint32_t voff = (uint32_t)((l & 7) + 8*(l >> 3)) * 144;

    unsigned short* p0 = g_p + ((size_t)bh*L + r0) * (size_t)L;
    unsigned short* p1 = g_p + ((size_t)bh*L + r1) * (size_t)L;

    float oacc[8][4] = {};
    float rs0 = 0.f, rs1 = 0.f;

    #pragma unroll
    for (int sgi = 0; sgi < 4; sgi++) cpa16(sdst + sgi*16, ssrc + sgi*8);
    CPCOMMIT();

    for (int it = 0; it < 64; it++) {
        const int kc = it * 64;
        CPWAIT0();
        __syncthreads();
        if (it + 1 < 64) {
            const int nb_ = (it + 1) & 1;
            const unsigned short* s2 = ssrc + (size_t)(kc + 64)*64;
            #pragma unroll
            for (int sgi = 0; sgi < 4; sgi++) cpa16(sdst + nb_*AT_BUF + sgi*16, s2 + sgi*8);
            CPCOMMIT();
        }
        const uint32_t bufb = sb + (it & 1)*AT_BUF;
        const uint32_t khb = bufb, vhb = bufb + 9216;

        uint32_t ph[4][4];
        #pragma unroll
        for (int j = 0; j < 8; j++) {
            uint32_t kb[8];
            uint32_t ah = khb + (uint32_t)(8*j)*144 + koff;
            ldsm4(kb[0], kb[1], kb[2], kb[3], ah);
            ldsm4(kb[4], kb[5], kb[6], kb[7], ah + 64);
            float sacc[4] = {0.f, 0.f, 0.f, 0.f};
            #pragma unroll
            for (int ks = 0; ks < 4; ks++)
                mma16816f(sacc, qh[ks], kb[2*ks], kb[2*ks+1]);
            float e0 = ex2(sacc[0]), e1 = ex2(sacc[1]);
            float e2 = ex2(sacc[2]), e3 = ex2(sacc[3]);
            int col = kc + 8*j + 2*cc;
            if (!ok0) {
                if (!mrow0[col])   e0 = 0.f;
                if (!mrow0[col+1]) e1 = 0.f;
            }
            if (!ok1) {
                if (!mrow1[col])   e2 = 0.f;
                if (!mrow1[col+1]) e3 = 0.f;
            }
            rs0 += e0 + e1; rs1 += e2 + e3;
            int t = j >> 1, o = (j & 1) * 2;
            uint32_t pk0 = packf16(e0, e1);
            uint32_t pk1 = packf16(e2, e3);
            ph[t][o]   = pk0;
            ph[t][o+1] = pk1;
            *(uint32_t*)(p0 + col) = pk0;
            *(uint32_t*)(p1 + col) = pk1;
        }
        #pragma unroll
        for (int jd = 0; jd < 8; jd++) {
            uint32_t vb[8];
            #pragma unroll
            for (int tp = 0; tp < 2; tp++) {
                uint32_t ahv = vhb + (uint32_t)(32*tp)*144 + voff + (uint32_t)jd*16;
                ldsm4t(vb[4*tp+0], vb[4*tp+1], vb[4*tp+2], vb[4*tp+3], ahv);
            }
            #pragma unroll
            for (int t = 0; t < 4; t++)
                mma16816f(oacc[jd], ph[t], vb[2*t], vb[2*t+1]);
        }
    }

    rs0 += __shfl_xor_sync(0xffffffffu, rs0, 1);
    rs0 += __shfl_xor_sync(0xffffffffu, rs0, 2);
    rs1 += __shfl_xor_sync(0xffffffffu, rs1, 1);
    rs1 += __shfl_xor_sync(0xffffffffu, rs1, 2);
    if (cc == 0) {
        g_rowsum[(size_t)bh*L + r0] = rs0;
        g_rowsum[(size_t)bh*L + r1] = rs1;
    }
    const float rinv0 = 1.f / rs0, rinv1 = 1.f / rs1;

    #pragma unroll
    for (int jd = 0; jd < 8; jd++) {
        int col = 8*jd + 2*cc;
        uint32_t hp, lp;
        packsplit(oacc[jd][0]*rinv0, oacc[jd][1]*rinv0, hp, lp);
        size_t i0 = ((size_t)bh*L + r0)*64 + col;
        *(uint32_t*)(g_aoh + i0) = hp; *(uint32_t*)(g_aol + i0) = lp;
        packsplit(oacc[jd][2]*rinv1, oacc[jd][3]*rinv1, hp, lp);
        size_t i1 = ((size_t)bh*L + r1)*64 + col;
        *(uint32_t*)(g_aoh + i1) = hp; *(uint32_t*)(g_aol + i1) = lp;
    }
}

// ---------- normalize: read fp16 P, scale, write fp32 wout (no smem) --------
__global__ void normalize_w(float* __restrict__ wout) {
    const int row = blockIdx.x;
    const float rinv = 1.f / g_rowsum[row];
    const uint2* src = (const uint2*)(g_p + (size_t)row * L);
    float4* dst = (float4*)(wout + (size_t)row * L);
    #pragma unroll
    for (int i = 0; i < 4; i++) {
        int idx = i*256 + threadIdx.x;
        uint2 pv = src[idx];
        float f0, f1, f2, f3;
        unpackf16(pv.x, f0, f1);
        unpackf16(pv.y, f2, f3);
        dst[idx] = make_float4(f0*rinv, f1*rinv, f2*rinv, f3*rinv);
    }
}

// ---------------- output projection via mma.sync bf16x3 --------------------
#define OP_AH 0
#define OP_AL 18432
#define OP_BH 36864
#define OP_BL 46080
#define OP_SZ 55296

__global__ void __launch_bounds__(256) outproj_mma(float* __restrict__ out) {
    extern __shared__ char smem[];
    const uint32_t sb = su32(smem);
    const int tid = threadIdx.x;
    const int w = tid >> 5, l = tid & 31;
    const int g = l >> 2, cc = l & 3;
    const int m0 = blockIdx.x * 128;
    const int n0 = blockIdx.y * 64;

    const int aarr = tid >> 7, arow = tid & 127;
    const int am = m0 + arow, ab = am >> 12, al_ = am & 4095;
    const unsigned short* asrc0 = (aarr ? g_aol : g_aoh);
    const uint32_t adst = sb + (aarr ? OP_AL : OP_AH) + arow*144;
    const int barr = tid >> 7, brow = (tid >> 1) & 63, bseg0 = (tid & 1) * 4;
    const unsigned short* bsrc = (barr ? g_wl : g_wh) + (size_t)3*262144 + (size_t)(n0 + brow)*512;
    const uint32_t bdst = sb + (barr ? OP_BL : OP_BH) + brow*144;

    float c[8][4] = {};
    for (int kt = 0; kt < 8; kt++) {
        const unsigned short* as = asrc0 + ((size_t)(ab*H + kt)*L + al_)*64;
        #pragma unroll
        for (int sgi = 0; sgi < 8; sgi++) cpa16(adst + sgi*16, as + sgi*8);
        #pragma unroll
        for (int i = 0; i < 4; i++) {
            int seg = bseg0 + i;
            cpa16(bdst + seg*16, bsrc + kt*64 + seg*8);
        }
        CPCOMMIT();
        CPWAIT0();
        __syncthreads();

        uint32_t ah[4][4], alr[4][4];
        const uint32_t aoff = (uint32_t)((l & 15) + 16*w) * 144 + (uint32_t)(l >> 4) * 16;
        #pragma unroll
        for (int ks = 0; ks < 4; ks++) {
            ldsm4(ah[ks][0],  ah[ks][1],  ah[ks][2],  ah[ks][3],  sb + OP_AH + aoff + ks*32);
            ldsm4(alr[ks][0], alr[ks][1], alr[ks][2], alr[ks][3], sb + OP_AL + aoff + ks*32);
        }
        const uint32_t boff = (uint32_t)(l & 7) * 144 + (uint32_t)(l >> 3) * 16;
        #pragma unroll
        for (int j = 0; j < 8; j++) {
            uint32_t kb[8], kbl[8];
            uint32_t bh_ = sb + OP_BH + (uint32_t)(8*j)*144 + boff;
            uint32_t bl_ = sb + OP_BL + (uint32_t)(8*j)*144 + boff;
            ldsm4(kb[0], kb[1], kb[2], kb[3], bh_);
            ldsm4(kb[4], kb[5], kb[6], kb[7], bh_ + 64);
            ldsm4(kbl[0], kbl[1], kbl[2], kbl[3], bl_);
            ldsm4(kbl[4], kbl[5], kbl[6], kbl[7], bl_ + 64);
            #pragma unroll
            for (int ks = 0; ks < 4; ks++) {
                mma16816(c[j], ah[ks],  kb[2*ks],  kb[2*ks+1]);
                mma16816(c[j], ah[ks],  kbl[2*ks], kbl[2*ks+1]);
                mma16816(c[j], alr[ks], kb[2*ks],  kb[2*ks+1]);
            }
        }
        __syncthreads();
    }

    const int r0 = m0 + 16*w + g, r1 = r0 + 8;
    #pragma unroll
    for (int j = 0; j < 8; j++) {
        int col = 8*j + 2*cc;
        float bia0 = g_wb[3*512 + n0 + col], bia1 = g_wb[3*512 + n0 + col + 1];
        *(float2*)(out + (size_t)r0*512 + n0 + col) = make_float2(c[j][0] + bia0, c[j][1] + bia1);
        *(float2*)(out + (size_t)r1*512 + n0 + col) = make_float2(c[j][2] + bia0, c[j][3] + bia1);
    }
}

extern "C" void kernel_launch(void* const* d_in, const int* in_sizes, int n_in,
                              void* d_out, int out_size) {
    const float* q    = (const float*)d_in[0];
    const float* k    = (const float*)d_in[1];
    const float* v    = (const float*)d_in[2];
    const int*   mask = (const int*)d_in[3];
    const float* Wq   = (const float*)d_in[4];
    const float* bq   = (const float*)d_in[5];
    const float* Wk   = (const float*)d_in[6];
    const float* bk   = (const float*)d_in[7];
    const float* Wv   = (const float*)d_in[8];
    const float* bv   = (const float*)d_in[9];
    const float* Wo   = (const float*)d_in[10];
    const float* bo   = (const float*)d_in[11];

    float* out  = (float*)d_out;                    // (N, L, 512)
    float* wout = out + (size_t)NB*L*D;             // (N, H, L, L)

    cudaFuncSetAttribute(proj_mma,    cudaFuncAttributeMaxDynamicSharedMemorySize, PJ_SZ);
    cudaFuncSetAttribute(attn_mma,    cudaFuncAttributeMaxDynamicSharedMemorySize, 2*AT_BUF);
    cudaFuncSetAttribute(outproj_mma, cudaFuncAttributeMaxDynamicSharedMemorySize, OP_SZ);

    mask_scan  <<<NB*L, 256>>>(mask);
    prep_w     <<<4096, 256>>>(Wq, Wk, Wv, Wo, bq, bk, bv, bo);
    proj_mma   <<<dim3(64,8,3), 256, PJ_SZ>>>(q, k, v);
    attn_mma   <<<dim3(32,8,2), 256, 2*AT_BUF>>>(mask);
    normalize_w<<<NB*H*L, 256>>>(wout);
    outproj_mma<<<dim3(64,8),   256, OP_SZ>>>(out);
}